// round 1
// baseline (speedup 1.0000x reference)
#include <cuda_runtime.h>
#include <math.h>

#define T_  256
#define B_  64
#define D_  1024
#define H_  1024
#define DH_ 2048
#define NG_ 4096   /* 4 gates * H */

// Scratch: x-projection for all timesteps/gates (256 MB), h double buffer, c state.
__device__ float g_zx[(size_t)T_ * B_ * NG_];
__device__ float g_h[2 * B_ * H_];
__device__ float g_c[B_ * H_];

// ---------------------------------------------------------------------------
// Phase 1: Z[(t*B+b), gate*H+j] = x[t,b,:] . W_gate[j, 0:D] + b_gate[j]
// Classic 128x128x16 fp32 SGEMM, 256 threads, 8x8 microtile.
// A (16384 x 1024) row-major; W rows are K-contiguous (NT gemm).
// ---------------------------------------------------------------------------
__global__ __launch_bounds__(256) void gemm_input(
    const float* __restrict__ X,
    const float* __restrict__ Wf, const float* __restrict__ Wi,
    const float* __restrict__ Wu, const float* __restrict__ Wo,
    const float* __restrict__ bf, const float* __restrict__ bi,
    const float* __restrict__ bu, const float* __restrict__ bo,
    float* __restrict__ Z)
{
    __shared__ float As[16][128];
    __shared__ float Bs[16][128];

    const int K  = D_;
    const int n0 = blockIdx.x * 128;
    const int m0 = blockIdx.y * 128;
    const int gate = n0 >> 10;
    const int j0   = n0 & (H_ - 1);

    const float* W;
    const float* bias;
    if      (gate == 0) { W = Wf; bias = bf; }
    else if (gate == 1) { W = Wi; bias = bi; }
    else if (gate == 2) { W = Wu; bias = bu; }
    else                { W = Wo; bias = bo; }

    const int tid = threadIdx.x;
    const int tx  = tid & 15;
    const int ty  = tid >> 4;
    const int lr  = tid >> 2;          // 0..63
    const int lk  = (tid & 3) << 2;    // 0,4,8,12

    float acc[8][8];
#pragma unroll
    for (int i = 0; i < 8; i++)
#pragma unroll
        for (int j = 0; j < 8; j++) acc[i][j] = 0.0f;

    for (int k0 = 0; k0 < K; k0 += 16) {
#pragma unroll
        for (int i = 0; i < 2; i++) {
            int row = lr + i * 64;
            float4 v = *(const float4*)(X + (size_t)(m0 + row) * K + k0 + lk);
            As[lk + 0][row] = v.x; As[lk + 1][row] = v.y;
            As[lk + 2][row] = v.z; As[lk + 3][row] = v.w;
        }
#pragma unroll
        for (int i = 0; i < 2; i++) {
            int row = lr + i * 64;
            float4 v = *(const float4*)(W + (size_t)(j0 + row) * DH_ + k0 + lk);
            Bs[lk + 0][row] = v.x; Bs[lk + 1][row] = v.y;
            Bs[lk + 2][row] = v.z; Bs[lk + 3][row] = v.w;
        }
        __syncthreads();

#pragma unroll
        for (int k = 0; k < 16; k++) {
            float4 a0 = *(const float4*)&As[k][ty * 8];
            float4 a1 = *(const float4*)&As[k][ty * 8 + 4];
            float4 b0 = *(const float4*)&Bs[k][tx * 8];
            float4 b1 = *(const float4*)&Bs[k][tx * 8 + 4];
            float a[8] = {a0.x, a0.y, a0.z, a0.w, a1.x, a1.y, a1.z, a1.w};
            float b[8] = {b0.x, b0.y, b0.z, b0.w, b1.x, b1.y, b1.z, b1.w};
#pragma unroll
            for (int i = 0; i < 8; i++)
#pragma unroll
                for (int j = 0; j < 8; j++) acc[i][j] += a[i] * b[j];
        }
        __syncthreads();
    }

#pragma unroll
    for (int i = 0; i < 8; i++) {
        int m = m0 + ty * 8 + i;
#pragma unroll
        for (int j = 0; j < 8; j++) {
            int n = n0 + tx * 8 + j;
            Z[(size_t)m * NG_ + n] = acc[i][j] + bias[n & (H_ - 1)];
        }
    }
}

// ---------------------------------------------------------------------------
// Phase 2: one fused step. 128 blocks; block bx owns j in [bx*8, bx*8+8) for
// ALL four gates (n = gate*8 + jl, 32 N-rows), M = 64 batches, K = 1024.
// 128 threads, 4x4 microtile. After the GEMM the block combines the four
// gates: f/i/g/o = act(cos(z)+gb), c = f*c + i*g, h = o*tanh(c).
// ---------------------------------------------------------------------------
__global__ __launch_bounds__(128) void lstm_step(
    const float* __restrict__ Zx,      // (B, 4096) slice for this t
    const float* __restrict__ Wf, const float* __restrict__ Wi,
    const float* __restrict__ Wu, const float* __restrict__ Wo,
    const float* __restrict__ gbf, const float* __restrict__ gbi,
    const float* __restrict__ gbu, const float* __restrict__ gbo,
    const float* __restrict__ h_in,
    float* __restrict__ h_out,
    float* __restrict__ c_io,
    float* __restrict__ out_t,
    float* __restrict__ hc_tail)       // null, or [hx | cx] region on last step
{
    __shared__ float Hs[16][64];
    __shared__ float Ws[16][32];
    __shared__ float Zs[64][32];

    const int tid = threadIdx.x;
    const int j0  = blockIdx.x * 8;
    const int tx  = tid & 7;     // n quad: n = tx*4 .. tx*4+3
    const int ty  = tid >> 3;    // b quad: b = ty*4 .. ty*4+3

    // W load assignment: 32 rows x 4 float4 each
    const int wrow = tid >> 2;            // 0..31 == n index
    const int wkc  = (tid & 3) << 2;
    const float* Wptr;
    {
        int gate = wrow >> 3;
        int j    = j0 + (wrow & 7);
        const float* W = (gate == 0) ? Wf : (gate == 1) ? Wi : (gate == 2) ? Wu : Wo;
        Wptr = W + (size_t)j * DH_ + D_ + wkc;   // h-part columns
    }

    float acc[4][4];
#pragma unroll
    for (int i = 0; i < 4; i++)
#pragma unroll
        for (int j = 0; j < 4; j++) acc[i][j] = 0.0f;

    for (int k0 = 0; k0 < H_; k0 += 16) {
#pragma unroll
        for (int i = 0; i < 2; i++) {
            int idx = tid + i * 128;
            int row = idx >> 2;              // 0..63 (batch)
            int kc  = (idx & 3) << 2;
            float4 v = *(const float4*)(h_in + (size_t)row * H_ + k0 + kc);
            Hs[kc + 0][row] = v.x; Hs[kc + 1][row] = v.y;
            Hs[kc + 2][row] = v.z; Hs[kc + 3][row] = v.w;
        }
        {
            float4 v = *(const float4*)(Wptr + k0);
            Ws[wkc + 0][wrow] = v.x; Ws[wkc + 1][wrow] = v.y;
            Ws[wkc + 2][wrow] = v.z; Ws[wkc + 3][wrow] = v.w;
        }
        __syncthreads();

#pragma unroll
        for (int k = 0; k < 16; k++) {
            float4 a4 = *(const float4*)&Hs[k][ty * 4];
            float4 b4 = *(const float4*)&Ws[k][tx * 4];
            float a[4] = {a4.x, a4.y, a4.z, a4.w};
            float b[4] = {b4.x, b4.y, b4.z, b4.w};
#pragma unroll
            for (int i = 0; i < 4; i++)
#pragma unroll
                for (int j = 0; j < 4; j++) acc[i][j] += a[i] * b[j];
        }
        __syncthreads();
    }

#pragma unroll
    for (int i = 0; i < 4; i++)
#pragma unroll
        for (int j = 0; j < 4; j++) Zs[ty * 4 + i][tx * 4 + j] = acc[i][j];
    __syncthreads();

    // Combine: 512 (b, jl) pairs, 4 per thread.
#pragma unroll
    for (int p0 = 0; p0 < 4; p0++) {
        int p  = tid + p0 * 128;   // 0..511
        int b  = p >> 3;
        int jl = p & 7;
        int j  = j0 + jl;
        const float* zxr = Zx + (size_t)b * NG_;

        float zf = Zs[b][0 * 8 + jl] + zxr[0 * H_ + j];
        float zi = Zs[b][1 * 8 + jl] + zxr[1 * H_ + j];
        float zu = Zs[b][2 * 8 + jl] + zxr[2 * H_ + j];
        float zo = Zs[b][3 * 8 + jl] + zxr[3 * H_ + j];

        float f  = 1.0f / (1.0f + expf(-(cosf(zf) + gbf[j])));
        float ig = 1.0f / (1.0f + expf(-(cosf(zi) + gbi[j])));
        float g  = tanhf(cosf(zu) + gbu[j]);
        float o  = 1.0f / (1.0f + expf(-(cosf(zo) + gbo[j])));

        size_t bidx = (size_t)b * H_ + j;
        float c = f * c_io[bidx] + ig * g;
        c_io[bidx] = c;
        float h = o * tanhf(c);
        h_out[bidx] = h;
        out_t[bidx] = h;
        if (hc_tail) {
            hc_tail[bidx] = h;
            hc_tail[(size_t)B_ * H_ + bidx] = c;
        }
    }
}

// ---------------------------------------------------------------------------
extern "C" void kernel_launch(void* const* d_in, const int* in_sizes, int n_in,
                              void* d_out, int out_size)
{
    const float* X   = (const float*)d_in[0];
    const float* Wf  = (const float*)d_in[1];
    const float* bf  = (const float*)d_in[2];
    const float* gbf = (const float*)d_in[3];
    const float* Wi  = (const float*)d_in[4];
    const float* bi  = (const float*)d_in[5];
    const float* gbi = (const float*)d_in[6];
    const float* Wu  = (const float*)d_in[7];
    const float* bu  = (const float*)d_in[8];
    const float* gbu = (const float*)d_in[9];
    const float* Wo  = (const float*)d_in[10];
    const float* bo  = (const float*)d_in[11];
    const float* gbo = (const float*)d_in[12];

    float* out = (float*)d_out;

    float *p_zx, *p_h, *p_c;
    cudaGetSymbolAddress((void**)&p_zx, g_zx);
    cudaGetSymbolAddress((void**)&p_h,  g_h);
    cudaGetSymbolAddress((void**)&p_c,  g_c);

    // h (parity 0) and c start at zero every call.
    cudaMemsetAsync(p_h, 0, sizeof(float) * B_ * H_);
    cudaMemsetAsync(p_c, 0, sizeof(float) * B_ * H_);

    // Phase 1: all-timestep input projection (+bias), 4 gates fused as N=4096.
    dim3 g1(NG_ / 128, (T_ * B_) / 128);
    gemm_input<<<g1, 256>>>(X, Wf, Wi, Wu, Wo, bf, bi, bu, bo, p_zx);

    // Phase 2: sequential recurrence, 256 fused step kernels.
    const size_t TBH = (size_t)T_ * B_ * H_;
    const bool tails = out_size >= (int)(TBH + 2 * (size_t)B_ * H_);
    for (int t = 0; t < T_; t++) {
        float* h_in    = p_h + (size_t)(t & 1) * B_ * H_;
        float* h_out   = p_h + (size_t)((t + 1) & 1) * B_ * H_;
        float* hc_tail = (tails && t == T_ - 1) ? out + TBH : nullptr;
        lstm_step<<<128, 128>>>(p_zx + (size_t)t * B_ * NG_,
                                Wf, Wi, Wu, Wo,
                                gbf, gbi, gbu, gbo,
                                h_in, h_out, p_c,
                                out + (size_t)t * B_ * H_,
                                hc_tail);
    }
}

// round 3
// speedup vs baseline: 2.2805x; 2.2805x over previous
#include <cuda_runtime.h>
#include <cuda_bf16.h>
#include <math.h>
#include <stdint.h>

#define T_  256
#define B_  64
#define D_  1024
#define H_  1024
#define DH_ 2048
#define NG_ 4096   /* 4 gates * H */

// ---------------------------------------------------------------------------
// Device globals (scratch; no runtime allocation allowed)
// ---------------------------------------------------------------------------
__device__ float g_zx[(size_t)T_ * B_ * NG_];          // 256 MB: x-projection
__device__ __nv_bfloat16 g_whh[(size_t)NG_ * H_];      // packed Wh hi, row n=(j<<2)|gate
__device__ __nv_bfloat16 g_whl[(size_t)NG_ * H_];      // packed Wh lo
__device__ __nv_bfloat16 g_hh[2][B_ * H_];             // h hi, double buffered
__device__ __nv_bfloat16 g_hl[2][B_ * H_];             // h lo
__device__ float g_c[B_ * H_];

// ---------------------------------------------------------------------------
// PTX helpers: portable (compute_103-legal) tensor path
// ---------------------------------------------------------------------------
__device__ __forceinline__ uint32_t smem_u32(const void* p) {
    uint32_t a;
    asm("{ .reg .u64 t; cvta.to.shared.u64 t, %1; cvt.u32.u64 %0, t; }" : "=r"(a) : "l"(p));
    return a;
}
__device__ __forceinline__ void cp_async16(uint32_t smem, const void* g) {
    asm volatile("cp.async.cg.shared.global [%0], [%1], 16;" :: "r"(smem), "l"(g) : "memory");
}
#define CP_COMMIT() asm volatile("cp.async.commit_group;" ::: "memory")
#define CP_WAIT(n)  asm volatile("cp.async.wait_group %0;" :: "n"(n) : "memory")

__device__ __forceinline__ void ldsm_x4(uint32_t& r0, uint32_t& r1, uint32_t& r2, uint32_t& r3,
                                        uint32_t addr) {
    asm volatile("ldmatrix.sync.aligned.m8n8.x4.shared.b16 {%0,%1,%2,%3}, [%4];"
                 : "=r"(r0), "=r"(r1), "=r"(r2), "=r"(r3) : "r"(addr));
}
__device__ __forceinline__ void mma_bf16(float* c,
                                         uint32_t a0, uint32_t a1, uint32_t a2, uint32_t a3,
                                         uint32_t b0, uint32_t b1) {
    asm volatile("mma.sync.aligned.m16n8k16.row.col.f32.bf16.bf16.f32 "
                 "{%0,%1,%2,%3}, {%4,%5,%6,%7}, {%8,%9}, {%0,%1,%2,%3};"
                 : "+f"(c[0]), "+f"(c[1]), "+f"(c[2]), "+f"(c[3])
                 : "r"(a0), "r"(a1), "r"(a2), "r"(a3), "r"(b0), "r"(b1));
}
#define SWZ(off) ((off) ^ (((off) >> 3) & 0x70))

// ---------------------------------------------------------------------------
// Phase 0: pre-convert Wh (h-part of W) into packed bf16 hi/lo.
// Packed row n = (j<<2) | gate so step-CTA bx owns rows [bx*32, bx*32+32)
// = j in [bx*8, bx*8+8), 4 gates adjacent per j.
// ---------------------------------------------------------------------------
__global__ __launch_bounds__(256) void conv_w(
    const float* __restrict__ Wf, const float* __restrict__ Wi,
    const float* __restrict__ Wu, const float* __restrict__ Wo,
    __nv_bfloat16* __restrict__ hi, __nv_bfloat16* __restrict__ lo)
{
    size_t idx = (size_t)blockIdx.x * 256 + threadIdx.x;   // over NG_*H_
    int n = (int)(idx >> 10);
    int k = (int)(idx & 1023);
    int j = n >> 2, gate = n & 3;
    const float* W = (gate == 0) ? Wf : (gate == 1) ? Wi : (gate == 2) ? Wu : Wo;
    float w = W[(size_t)j * DH_ + D_ + k];
    __nv_bfloat16 h16 = __float2bfloat16(w);
    hi[idx] = h16;
    lo[idx] = __float2bfloat16(w - __bfloat162float(h16));
}

// ---------------------------------------------------------------------------
// Phase 1: input projection (all timesteps), fp32 SGEMM 128x128x16.
// ---------------------------------------------------------------------------
__global__ __launch_bounds__(256) void gemm_input(
    const float* __restrict__ X,
    const float* __restrict__ Wf, const float* __restrict__ Wi,
    const float* __restrict__ Wu, const float* __restrict__ Wo,
    const float* __restrict__ bf, const float* __restrict__ bi,
    const float* __restrict__ bu, const float* __restrict__ bo,
    float* __restrict__ Z)
{
    __shared__ float As[16][128];
    __shared__ float Bs[16][128];

    const int K  = D_;
    const int n0 = blockIdx.x * 128;
    const int m0 = blockIdx.y * 128;
    const int gate = n0 >> 10;
    const int j0   = n0 & (H_ - 1);

    const float* W;
    const float* bias;
    if      (gate == 0) { W = Wf; bias = bf; }
    else if (gate == 1) { W = Wi; bias = bi; }
    else if (gate == 2) { W = Wu; bias = bu; }
    else                { W = Wo; bias = bo; }

    const int tid = threadIdx.x;
    const int tx  = tid & 15;
    const int ty  = tid >> 4;
    const int lr  = tid >> 2;
    const int lk  = (tid & 3) << 2;

    float acc[8][8];
#pragma unroll
    for (int i = 0; i < 8; i++)
#pragma unroll
        for (int j = 0; j < 8; j++) acc[i][j] = 0.0f;

    for (int k0 = 0; k0 < K; k0 += 16) {
#pragma unroll
        for (int i = 0; i < 2; i++) {
            int row = lr + i * 64;
            float4 v = *(const float4*)(X + (size_t)(m0 + row) * K + k0 + lk);
            As[lk + 0][row] = v.x; As[lk + 1][row] = v.y;
            As[lk + 2][row] = v.z; As[lk + 3][row] = v.w;
        }
#pragma unroll
        for (int i = 0; i < 2; i++) {
            int row = lr + i * 64;
            float4 v = *(const float4*)(W + (size_t)(j0 + row) * DH_ + k0 + lk);
            Bs[lk + 0][row] = v.x; Bs[lk + 1][row] = v.y;
            Bs[lk + 2][row] = v.z; Bs[lk + 3][row] = v.w;
        }
        __syncthreads();

#pragma unroll
        for (int k = 0; k < 16; k++) {
            float4 a0 = *(const float4*)&As[k][ty * 8];
            float4 a1 = *(const float4*)&As[k][ty * 8 + 4];
            float4 b0 = *(const float4*)&Bs[k][tx * 8];
            float4 b1 = *(const float4*)&Bs[k][tx * 8 + 4];
            float a[8] = {a0.x, a0.y, a0.z, a0.w, a1.x, a1.y, a1.z, a1.w};
            float b[8] = {b0.x, b0.y, b0.z, b0.w, b1.x, b1.y, b1.z, b1.w};
#pragma unroll
            for (int i = 0; i < 8; i++)
#pragma unroll
                for (int j = 0; j < 8; j++) acc[i][j] += a[i] * b[j];
        }
        __syncthreads();
    }

#pragma unroll
    for (int i = 0; i < 8; i++) {
        int m = m0 + ty * 8 + i;
#pragma unroll
        for (int j = 0; j < 8; j++) {
            int n = n0 + tx * 8 + j;
            Z[(size_t)m * NG_ + n] = acc[i][j] + bias[n & (H_ - 1)];
        }
    }
}

// ---------------------------------------------------------------------------
// Phase 2: one recurrence step on tensor cores (mma.sync bf16, split hi/lo).
// Per CTA (128 CTAs): D(64x32) = h(64x1024) @ Wslice(32x1024)^T with
//   D = Ah*Bh + Ah*Bl + Al*Bh  accumulated in fp32 registers.
// K chunked by 64, 2-stage cp.async double buffer. Fused LSTM epilogue.
// SMEM layout (49152 B dynamic):
//   [0,8K)=A_hi s0  [8K,16K)=A_hi s1  [16K,24K)=A_lo s0 [24K,32K)=A_lo s1
//   [32K,36K)=B_hi s0 [36K,40K)=B_hi s1 [40K,44K)=B_lo s0 [44K,48K)=B_lo s1
//   Zs(64x32 f32, 8K) overlays offset 0 after the mainloop.
// ---------------------------------------------------------------------------
#define A_HI(s) ((s) * 8192)
#define A_LO(s) (16384 + (s) * 8192)
#define B_HI(s) (32768 + (s) * 4096)
#define B_LO(s) (40960 + (s) * 4096)
#define SMEM_DYN_ 49152
#define NCH_ 16   /* 1024 / 64 */

__device__ __forceinline__ float sigf(float x) { return 1.0f / (1.0f + expf(-x)); }

__global__ __launch_bounds__(128) void lstm_step(
    const float* __restrict__ Zx,                 // (B, 4096) slice for this t
    const __nv_bfloat16* __restrict__ Whh,        // packed (4096,1024) hi
    const __nv_bfloat16* __restrict__ Whl,        // packed lo
    const __nv_bfloat16* __restrict__ hh_in,      // (64,1024) bf16 hi
    const __nv_bfloat16* __restrict__ hl_in,
    __nv_bfloat16* __restrict__ hh_out,
    __nv_bfloat16* __restrict__ hl_out,
    const float* __restrict__ gbf, const float* __restrict__ gbi,
    const float* __restrict__ gbu, const float* __restrict__ gbo,
    float* __restrict__ c_io,
    float* __restrict__ out_t,
    float* __restrict__ hc_tail)
{
    extern __shared__ __align__(128) char sm[];
    const uint32_t sbase = smem_u32(sm);

    const int tid  = threadIdx.x;
    const int wid  = tid >> 5;
    const int lane = tid & 31;
    const int bx   = blockIdx.x;

    const char* hh8 = (const char*)hh_in;
    const char* hl8 = (const char*)hl_in;
    const char* wh8 = (const char*)(Whh + (size_t)bx * 32 * H_);
    const char* wl8 = (const char*)(Whl + (size_t)bx * 32 * H_);

    // per-thread load slots
    const int a_row = tid >> 3;          // used as idx>>3 below
    const int a_cg  = tid & 7;

    // issue loads for chunk t into stage s
    auto load_chunk = [&](int t, int s) {
#pragma unroll
        for (int r = 0; r < 4; r++) {            // A: 512 slots (64 rows x 8)
            int idx = tid + r * 128;
            int row = idx >> 3;
            int cg  = idx & 7;
            size_t goff = (size_t)row * (H_ * 2) + (size_t)t * 128 + cg * 16;
            uint32_t soff = SWZ((uint32_t)(row * 128 + cg * 16));
            cp_async16(sbase + A_HI(s) + soff, hh8 + goff);
            cp_async16(sbase + A_LO(s) + soff, hl8 + goff);
        }
#pragma unroll
        for (int r = 0; r < 2; r++) {            // B: 256 slots (32 rows x 8)
            int idx = tid + r * 128;
            int row = idx >> 3;
            int cg  = idx & 7;
            size_t goff = (size_t)row * (H_ * 2) + (size_t)t * 128 + cg * 16;
            uint32_t soff = SWZ((uint32_t)(row * 128 + cg * 16));
            cp_async16(sbase + B_HI(s) + soff, wh8 + goff);
            cp_async16(sbase + B_LO(s) + soff, wl8 + goff);
        }
    };

    float acc[4][4];
#pragma unroll
    for (int nt = 0; nt < 4; nt++)
#pragma unroll
        for (int i = 0; i < 4; i++) acc[nt][i] = 0.0f;

    // ldmatrix lane-derived address components
    const int m0     = wid * 16;                    // warp's batch rows
    const uint32_t a_r  = (uint32_t)(m0 + (lane & 15));
    const uint32_t a_kb = (uint32_t)((lane >> 4) << 3);      // 0 or 8 (k offset)
    const uint32_t b_g  = (uint32_t)(lane >> 3);             // 0..3
    const uint32_t b_nt = b_g >> 1;                          // 0/1 within nt-pair
    const uint32_t b_kb = (b_g & 1) * 8;
    const uint32_t b_r  = (uint32_t)(lane & 7);

    load_chunk(0, 0);
    CP_COMMIT();

    for (int t = 0; t < NCH_; t++) {
        const int s = t & 1;
        if (t + 1 < NCH_) {
            load_chunk(t + 1, s ^ 1);
            CP_COMMIT();
            CP_WAIT(1);
        } else {
            CP_WAIT(0);
        }
        __syncthreads();

        const uint32_t Ah = sbase + A_HI(s), Al = sbase + A_LO(s);
        const uint32_t Bh = sbase + B_HI(s), Bl = sbase + B_LO(s);

#pragma unroll
        for (int ks = 0; ks < 4; ks++) {
            uint32_t aoff = SWZ((a_r << 7) + (ks * 16 + a_kb) * 2);
            uint32_t ah0, ah1, ah2, ah3, al0, al1, al2, al3;
            ldsm_x4(ah0, ah1, ah2, ah3, Ah + aoff);
            ldsm_x4(al0, al1, al2, al3, Al + aoff);

            uint32_t bh[8], bl[8];   // [nt*2 + (b0|b1)]
#pragma unroll
            for (int np = 0; np < 2; np++) {
                uint32_t row = (np * 2 + b_nt) * 8 + b_r;
                uint32_t boff = SWZ((row << 7) + (ks * 16 + b_kb) * 2);
                ldsm_x4(bh[np * 4 + 0], bh[np * 4 + 1], bh[np * 4 + 2], bh[np * 4 + 3], Bh + boff);
                ldsm_x4(bl[np * 4 + 0], bl[np * 4 + 1], bl[np * 4 + 2], bl[np * 4 + 3], Bl + boff);
            }
#pragma unroll
            for (int nt = 0; nt < 4; nt++) {
                mma_bf16(acc[nt], ah0, ah1, ah2, ah3, bh[nt * 2], bh[nt * 2 + 1]);
                mma_bf16(acc[nt], ah0, ah1, ah2, ah3, bl[nt * 2], bl[nt * 2 + 1]);
                mma_bf16(acc[nt], al0, al1, al2, al3, bh[nt * 2], bh[nt * 2 + 1]);
            }
        }
        __syncthreads();
    }

    // stage accumulators to SMEM (overlay offset 0) for cross-warp epilogue
    float* Zs = (float*)sm;   // [64][32]
    {
        const int g  = lane >> 2;
        const int tg = lane & 3;
#pragma unroll
        for (int nt = 0; nt < 4; nt++) {
            int n = nt * 8 + tg * 2;
            Zs[(m0 + g)     * 32 + n]     = acc[nt][0];
            Zs[(m0 + g)     * 32 + n + 1] = acc[nt][1];
            Zs[(m0 + g + 8) * 32 + n]     = acc[nt][2];
            Zs[(m0 + g + 8) * 32 + n + 1] = acc[nt][3];
        }
    }
    __syncthreads();

    // fused LSTM epilogue: 512 (b, jl) pairs, 4 per thread
    const int j0 = bx * 8;
#pragma unroll
    for (int p0 = 0; p0 < 4; p0++) {
        int p  = tid + p0 * 128;
        int b  = p >> 3;
        int jl = p & 7;
        int j  = j0 + jl;
        const float* zxr = Zx + (size_t)b * NG_;
        const float* zr  = Zs + b * 32 + jl * 4;

        float zf = zr[0] + zxr[0 * H_ + j];
        float zi = zr[1] + zxr[1 * H_ + j];
        float zu = zr[2] + zxr[2 * H_ + j];
        float zo = zr[3] + zxr[3 * H_ + j];

        float f  = sigf(cosf(zf) + gbf[j]);
        float ii = sigf(cosf(zi) + gbi[j]);
        float g  = tanhf(cosf(zu) + gbu[j]);
        float o  = sigf(cosf(zo) + gbo[j]);

        size_t idx = (size_t)b * H_ + j;
        float c = f * c_io[idx] + ii * g;
        c_io[idx] = c;
        float h = o * tanhf(c);
        out_t[idx] = h;

        __nv_bfloat16 hhi = __float2bfloat16(h);
        hh_out[idx] = hhi;
        hl_out[idx] = __float2bfloat16(h - __bfloat162float(hhi));

        if (hc_tail) {
            hc_tail[idx] = h;
            hc_tail[(size_t)B_ * H_ + idx] = c;
        }
    }
}

// ---------------------------------------------------------------------------
extern "C" void kernel_launch(void* const* d_in, const int* in_sizes, int n_in,
                              void* d_out, int out_size)
{
    const float* X   = (const float*)d_in[0];
    const float* Wf  = (const float*)d_in[1];
    const float* bf  = (const float*)d_in[2];
    const float* gbf = (const float*)d_in[3];
    const float* Wi  = (const float*)d_in[4];
    const float* bi  = (const float*)d_in[5];
    const float* gbi = (const float*)d_in[6];
    const float* Wu  = (const float*)d_in[7];
    const float* bu  = (const float*)d_in[8];
    const float* gbu = (const float*)d_in[9];
    const float* Wo  = (const float*)d_in[10];
    const float* bo  = (const float*)d_in[11];
    const float* gbo = (const float*)d_in[12];

    float* out = (float*)d_out;

    float *p_zx, *p_c;
    __nv_bfloat16 *p_whh, *p_whl, *p_hh, *p_hl;
    cudaGetSymbolAddress((void**)&p_zx,  g_zx);
    cudaGetSymbolAddress((void**)&p_c,   g_c);
    cudaGetSymbolAddress((void**)&p_whh, g_whh);
    cudaGetSymbolAddress((void**)&p_whl, g_whl);
    cudaGetSymbolAddress((void**)&p_hh,  g_hh);
    cudaGetSymbolAddress((void**)&p_hl,  g_hl);

    // zero initial h (parity 0) and c
    cudaMemsetAsync(p_hh, 0, sizeof(__nv_bfloat16) * B_ * H_);
    cudaMemsetAsync(p_hl, 0, sizeof(__nv_bfloat16) * B_ * H_);
    cudaMemsetAsync(p_c,  0, sizeof(float) * B_ * H_);

    // Phase 0: pack + split recurrent weights to bf16 hi/lo
    conv_w<<<(NG_ * H_) / 256, 256>>>(Wf, Wi, Wu, Wo, p_whh, p_whl);

    // Phase 1: all-timestep input projection (+bias)
    dim3 g1(NG_ / 128, (T_ * B_) / 128);
    gemm_input<<<g1, 256>>>(X, Wf, Wi, Wu, Wo, bf, bi, bu, bo, p_zx);

    // Phase 2: sequential recurrence on tensor cores
    const size_t TBH = (size_t)T_ * B_ * H_;
    const bool tails = out_size >= (int)(TBH + 2 * (size_t)B_ * H_);
    for (int t = 0; t < T_; t++) {
        __nv_bfloat16* hh_in  = p_hh + (size_t)(t & 1) * B_ * H_;
        __nv_bfloat16* hl_in  = p_hl + (size_t)(t & 1) * B_ * H_;
        __nv_bfloat16* hh_out = p_hh + (size_t)((t + 1) & 1) * B_ * H_;
        __nv_bfloat16* hl_out = p_hl + (size_t)((t + 1) & 1) * B_ * H_;
        float* hc_tail = (tails && t == T_ - 1) ? out + TBH : nullptr;
        lstm_step<<<128, 128, SMEM_DYN_>>>(
            p_zx + (size_t)t * B_ * NG_,
            p_whh, p_whl, hh_in, hl_in, hh_out, hl_out,
            gbf, gbi, gbu, gbo,
            p_c, out + (size_t)t * B_ * H_, hc_tail);
    }
}

// round 4
// speedup vs baseline: 2.6063x; 1.1429x over previous
#include <cuda_runtime.h>
#include <cuda_bf16.h>
#include <math.h>
#include <stdint.h>

#define T_  256
#define B_  64
#define D_  1024
#define H_  1024
#define DH_ 2048
#define NG_ 4096   /* 4 gates * H, packed n = j*4 + gate */
#define BH_ (B_ * H_)

// ---------------------------------------------------------------------------
// Device globals (scratch; no runtime allocation allowed)
// ---------------------------------------------------------------------------
__device__ float g_zx[(size_t)T_ * B_ * NG_];          // 256 MB: x-projection (packed cols)
__device__ __nv_bfloat16 g_whh[(size_t)NG_ * H_];      // packed Wh hi, row n=(j<<2)|gate
__device__ __nv_bfloat16 g_whl[(size_t)NG_ * H_];      // packed Wh lo
__device__ __nv_bfloat16 g_hh[2][BH_];                 // h hi, double buffered
__device__ __nv_bfloat16 g_hl[2][BH_];                 // h lo
__device__ unsigned g_bar;                             // grid barrier counter

// ---------------------------------------------------------------------------
// PTX helpers (compute_103-portable)
// ---------------------------------------------------------------------------
__device__ __forceinline__ uint32_t smem_u32(const void* p) {
    uint32_t a;
    asm("{ .reg .u64 t; cvta.to.shared.u64 t, %1; cvt.u32.u64 %0, t; }" : "=r"(a) : "l"(p));
    return a;
}
__device__ __forceinline__ void cp_async16(uint32_t smem, const void* g) {
    asm volatile("cp.async.cg.shared.global [%0], [%1], 16;" :: "r"(smem), "l"(g) : "memory");
}
#define CP_COMMIT() asm volatile("cp.async.commit_group;" ::: "memory")
#define CP_WAIT(n)  asm volatile("cp.async.wait_group %0;" :: "n"(n) : "memory")

__device__ __forceinline__ void ldsm_x4(uint32_t& r0, uint32_t& r1, uint32_t& r2, uint32_t& r3,
                                        uint32_t addr) {
    asm volatile("ldmatrix.sync.aligned.m8n8.x4.shared.b16 {%0,%1,%2,%3}, [%4];"
                 : "=r"(r0), "=r"(r1), "=r"(r2), "=r"(r3) : "r"(addr));
}
__device__ __forceinline__ void mma_bf16(float* c,
                                         uint32_t a0, uint32_t a1, uint32_t a2, uint32_t a3,
                                         uint32_t b0, uint32_t b1) {
    asm volatile("mma.sync.aligned.m16n8k16.row.col.f32.bf16.bf16.f32 "
                 "{%0,%1,%2,%3}, {%4,%5,%6,%7}, {%8,%9}, {%0,%1,%2,%3};"
                 : "+f"(c[0]), "+f"(c[1]), "+f"(c[2]), "+f"(c[3])
                 : "r"(a0), "r"(a1), "r"(a2), "r"(a3), "r"(b0), "r"(b1));
}
#define SWZ(off) ((off) ^ (((off) >> 3) & 0x70))

__device__ __forceinline__ float sigf(float x) { return 1.0f / (1.0f + __expf(-x)); }
__device__ __forceinline__ float tanh_fast(float x) {
    float a = fabsf(x);
    float e = __expf(-2.0f * a);
    float t = (1.0f - e) / (1.0f + e);
    return copysignf(t, x);
}

// ---------------------------------------------------------------------------
// Phase 0: pre-convert Wh (h-part) into packed bf16 hi/lo. Row n=(j<<2)|gate.
// ---------------------------------------------------------------------------
__global__ __launch_bounds__(256) void conv_w(
    const float* __restrict__ Wf, const float* __restrict__ Wi,
    const float* __restrict__ Wu, const float* __restrict__ Wo,
    __nv_bfloat16* __restrict__ hi, __nv_bfloat16* __restrict__ lo)
{
    size_t idx = (size_t)blockIdx.x * 256 + threadIdx.x;   // over NG_*H_
    int n = (int)(idx >> 10);
    int k = (int)(idx & 1023);
    int j = n >> 2, gate = n & 3;
    const float* W = (gate == 0) ? Wf : (gate == 1) ? Wi : (gate == 2) ? Wu : Wo;
    float w = W[(size_t)j * DH_ + D_ + k];
    __nv_bfloat16 h16 = __float2bfloat16(w);
    hi[idx] = h16;
    lo[idx] = __float2bfloat16(w - __bfloat162float(h16));
}

// ---------------------------------------------------------------------------
// Phase 1: input projection for all timesteps, fp32 SGEMM 128x128x16.
// Output columns are PACKED: Z[m][j*4+gate]. A CTA's 128 packed columns
// cover j in [n0/4, n0/4+32) for all 4 gates.
// ---------------------------------------------------------------------------
__global__ __launch_bounds__(256) void gemm_input(
    const float* __restrict__ X,
    const float* __restrict__ Wf, const float* __restrict__ Wi,
    const float* __restrict__ Wu, const float* __restrict__ Wo,
    const float* __restrict__ bf, const float* __restrict__ bi,
    const float* __restrict__ bu, const float* __restrict__ bo,
    float* __restrict__ Z)
{
    __shared__ float As[16][128];
    __shared__ float Bs[16][128];

    const int K  = D_;
    const int n0 = blockIdx.x * 128;   // packed col base (multiple of 128)
    const int m0 = blockIdx.y * 128;

    const int tid = threadIdx.x;
    const int tx  = tid & 15;
    const int ty  = tid >> 4;
    const int lr  = tid >> 2;
    const int lk  = (tid & 3) << 2;

    // B row r (packed): gate = r&3 (constant per thread), j = n0/4 + (r>>2)
    const int gsel = lr & 3;
    const float* Wg = (gsel == 0) ? Wf : (gsel == 1) ? Wi : (gsel == 2) ? Wu : Wo;

    float acc[8][8];
#pragma unroll
    for (int i = 0; i < 8; i++)
#pragma unroll
        for (int j = 0; j < 8; j++) acc[i][j] = 0.0f;

    for (int k0 = 0; k0 < K; k0 += 16) {
#pragma unroll
        for (int i = 0; i < 2; i++) {
            int row = lr + i * 64;
            float4 v = *(const float4*)(X + (size_t)(m0 + row) * K + k0 + lk);
            As[lk + 0][row] = v.x; As[lk + 1][row] = v.y;
            As[lk + 2][row] = v.z; As[lk + 3][row] = v.w;
        }
#pragma unroll
        for (int i = 0; i < 2; i++) {
            int row = lr + i * 64;
            int j   = (n0 >> 2) + (row >> 2);
            float4 v = *(const float4*)(Wg + (size_t)j * DH_ + k0 + lk);
            Bs[lk + 0][row] = v.x; Bs[lk + 1][row] = v.y;
            Bs[lk + 2][row] = v.z; Bs[lk + 3][row] = v.w;
        }
        __syncthreads();

#pragma unroll
        for (int k = 0; k < 16; k++) {
            float4 a0 = *(const float4*)&As[k][ty * 8];
            float4 a1 = *(const float4*)&As[k][ty * 8 + 4];
            float4 b0 = *(const float4*)&Bs[k][tx * 8];
            float4 b1 = *(const float4*)&Bs[k][tx * 8 + 4];
            float a[8] = {a0.x, a0.y, a0.z, a0.w, a1.x, a1.y, a1.z, a1.w};
            float b[8] = {b0.x, b0.y, b0.z, b0.w, b1.x, b1.y, b1.z, b1.w};
#pragma unroll
            for (int i = 0; i < 8; i++)
#pragma unroll
                for (int j = 0; j < 8; j++) acc[i][j] += a[i] * b[j];
        }
        __syncthreads();
    }

#pragma unroll
    for (int i = 0; i < 8; i++) {
        int m = m0 + ty * 8 + i;
#pragma unroll
        for (int jj = 0; jj < 8; jj++) {
            int n    = n0 + tx * 8 + jj;
            int gate = n & 3;
            int j    = n >> 2;
            const float* Ba = (gate == 0) ? bf : (gate == 1) ? bi : (gate == 2) ? bu : bo;
            Z[(size_t)m * NG_ + n] = acc[i][jj] + Ba[j];
        }
    }
}

// ---------------------------------------------------------------------------
// Phase 2: persistent recurrence. 128 CTAs (1/SM), 128 threads.
// CTA bx: weights rows [bx*32, bx*32+32) resident in SMEM (hi+lo = 128 KB).
// Per step: D(64x32) = Ah*Bh + Ah*Bl + Al*Bh (fp32 regs), fused LSTM epilogue,
// c in registers, release/acquire grid barrier between steps.
// SMEM: W_hi 0..64K | W_lo 64K..128K | A 3 stages x (8K hi + 8K lo) | ZX 8K
// Zs epilogue overlays A stage 0.
// ---------------------------------------------------------------------------
#define NST_      3
#define W_HI_     0
#define W_LO_     65536
#define A_HI_(s)  (131072 + (s) * 16384)
#define A_LO_(s)  (131072 + (s) * 16384 + 8192)
#define ZX_OFF_   180224
#define ZS_OFF_   131072
#define SMEM_DYN_ 188416

__global__ __launch_bounds__(128) void lstm_persist(
    const float* __restrict__ Zx_all,
    const __nv_bfloat16* __restrict__ Whh,
    const __nv_bfloat16* __restrict__ Whl,
    __nv_bfloat16* __restrict__ hh,    // [2][BH_]
    __nv_bfloat16* __restrict__ hl,
    const float* __restrict__ gbf, const float* __restrict__ gbi,
    const float* __restrict__ gbu, const float* __restrict__ gbo,
    float* __restrict__ out,           // [T][B][H]
    float* __restrict__ hc_tail)       // null or [hx|cx]
{
    extern __shared__ __align__(1024) char sm[];
    __shared__ float s_gb[32];

    const uint32_t sbase = smem_u32(sm);
    const int tid  = threadIdx.x;
    const int wid  = tid >> 5;
    const int lane = tid & 31;
    const int bx   = blockIdx.x;
    const int j0   = bx * 8;

    if (tid < 32) {
        int gate = tid >> 3, jl = tid & 7;
        const float* gp = (gate == 0) ? gbf : (gate == 1) ? gbi : (gate == 2) ? gbu : gbo;
        s_gb[tid] = gp[j0 + jl];
    }

    // ---- load resident weights once: 32 rows x 1024 k x (hi+lo) ----
    {
        const char* wh8 = (const char*)(Whh + (size_t)bx * 32 * H_);
        const char* wl8 = (const char*)(Whl + (size_t)bx * 32 * H_);
        for (int i = tid; i < 4096; i += 128) {     // 16 chunks * 32 rows * 8 cg
            int c  = i >> 8;
            int r  = (i >> 3) & 31;
            int cg = i & 7;
            size_t goff = (size_t)r * 2048 + (size_t)c * 128 + cg * 16;
            uint32_t soff = (uint32_t)c * 4096 + SWZ((uint32_t)(r * 128 + cg * 16));
            cp_async16(sbase + W_HI_ + soff, wh8 + goff);
            cp_async16(sbase + W_LO_ + soff, wl8 + goff);
        }
        CP_COMMIT(); CP_WAIT(0);
        __syncthreads();
    }

    // ldmatrix lane-derived components (as round 3)
    const int m0      = wid * 16;
    const uint32_t a_r  = (uint32_t)(m0 + (lane & 15));
    const uint32_t a_kb = (uint32_t)((lane >> 4) << 3);
    const uint32_t b_nt = (uint32_t)((lane >> 3) >> 1);
    const uint32_t b_kb = (uint32_t)(((lane >> 3) & 1) * 8);
    const uint32_t b_r  = (uint32_t)(lane & 7);

    float c_reg[4] = {0.f, 0.f, 0.f, 0.f};

    for (int t = 0; t < T_; t++) {
        const char* hh8 = (const char*)(hh + (size_t)(t & 1) * BH_);
        const char* hl8 = (const char*)(hl + (size_t)(t & 1) * BH_);
        __nv_bfloat16* hh_o = hh + (size_t)((t + 1) & 1) * BH_;
        __nv_bfloat16* hl_o = hl + (size_t)((t + 1) & 1) * BH_;
        const float* zx_t = Zx_all + (size_t)t * B_ * NG_;

        auto load_A = [&](int ch, int s) {
#pragma unroll
            for (int r4 = 0; r4 < 4; r4++) {
                int idx = tid + r4 * 128;
                int row = idx >> 3, cg = idx & 7;
                size_t goff = (size_t)row * 2048 + (size_t)ch * 128 + cg * 16;
                uint32_t soff = SWZ((uint32_t)(row * 128 + cg * 16));
                cp_async16(sbase + A_HI_(s) + soff, hh8 + goff);
                cp_async16(sbase + A_LO_(s) + soff, hl8 + goff);
            }
        };

        // prologue: ZX slab + chunk0 in group0, chunk1 in group1
#pragma unroll
        for (int r4 = 0; r4 < 4; r4++) {
            int slot = tid + r4 * 128;      // 512 = 64 b * 8 cg
            int b = slot >> 3, cg = slot & 7;
            const char* src = (const char*)(zx_t + (size_t)b * NG_ + bx * 32) + cg * 16;
            cp_async16(sbase + ZX_OFF_ + (uint32_t)(b * 128 + cg * 16), src);
        }
        load_A(0, 0); CP_COMMIT();
        load_A(1, 1); CP_COMMIT();

        float acc[4][4];
#pragma unroll
        for (int nt = 0; nt < 4; nt++)
#pragma unroll
            for (int i = 0; i < 4; i++) acc[nt][i] = 0.0f;

        for (int ch = 0; ch < 16; ch++) {
            const int s = ch % NST_;
            if (ch + 2 < 16) { load_A(ch + 2, (ch + 2) % NST_); CP_COMMIT(); CP_WAIT(2); }
            else if (ch == 14) { CP_WAIT(1); }
            else { CP_WAIT(0); }
            __syncthreads();

            const uint32_t Ah = sbase + A_HI_(s), Al = sbase + A_LO_(s);
            const uint32_t Bh = sbase + W_HI_ + (uint32_t)ch * 4096;
            const uint32_t Bl = sbase + W_LO_ + (uint32_t)ch * 4096;

#pragma unroll
            for (int ks = 0; ks < 4; ks++) {
                uint32_t aoff = SWZ((a_r << 7) + (ks * 16 + a_kb) * 2);
                uint32_t ah0, ah1, ah2, ah3, al0, al1, al2, al3;
                ldsm_x4(ah0, ah1, ah2, ah3, Ah + aoff);
                ldsm_x4(al0, al1, al2, al3, Al + aoff);

                uint32_t bh[8], bl[8];
#pragma unroll
                for (int np = 0; np < 2; np++) {
                    uint32_t row = (np * 2 + b_nt) * 8 + b_r;
                    uint32_t boff = SWZ((row << 7) + (ks * 16 + b_kb) * 2);
                    ldsm_x4(bh[np*4+0], bh[np*4+1], bh[np*4+2], bh[np*4+3], Bh + boff);
                    ldsm_x4(bl[np*4+0], bl[np*4+1], bl[np*4+2], bl[np*4+3], Bl + boff);
                }
#pragma unroll
                for (int nt = 0; nt < 4; nt++) {
                    mma_bf16(acc[nt], ah0, ah1, ah2, ah3, bh[nt*2], bh[nt*2+1]);
                    mma_bf16(acc[nt], ah0, ah1, ah2, ah3, bl[nt*2], bl[nt*2+1]);
                    mma_bf16(acc[nt], al0, al1, al2, al3, bh[nt*2], bh[nt*2+1]);
                }
            }
            __syncthreads();
        }

        // stage accumulators to SMEM (overlay A stage 0)
        float* Zs = (float*)(sm + ZS_OFF_);
        {
            const int g  = lane >> 2;
            const int tg = lane & 3;
#pragma unroll
            for (int nt = 0; nt < 4; nt++) {
                int n = nt * 8 + tg * 2;
                Zs[(m0 + g)     * 32 + n]     = acc[nt][0];
                Zs[(m0 + g)     * 32 + n + 1] = acc[nt][1];
                Zs[(m0 + g + 8) * 32 + n]     = acc[nt][2];
                Zs[(m0 + g + 8) * 32 + n + 1] = acc[nt][3];
            }
        }
        __syncthreads();

        // fused LSTM epilogue: 512 (b, jl) pairs, 4 per thread, c in registers
        const float* zxs = (const float*)(sm + ZX_OFF_);
        float* out_t = out + (size_t)t * BH_;
#pragma unroll
        for (int p0 = 0; p0 < 4; p0++) {
            int p  = tid + p0 * 128;
            int b  = p >> 3;
            int jl = p & 7;
            float4 zh  = *(const float4*)&Zs[b * 32 + jl * 4];
            float4 zx4 = *(const float4*)&zxs[b * 32 + jl * 4];

            float f  = sigf(__cosf(zh.x + zx4.x) + s_gb[0 * 8 + jl]);
            float ii = sigf(__cosf(zh.y + zx4.y) + s_gb[1 * 8 + jl]);
            float g  = tanh_fast(__cosf(zh.z + zx4.z) + s_gb[2 * 8 + jl]);
            float o  = sigf(__cosf(zh.w + zx4.w) + s_gb[3 * 8 + jl]);

            float c = f * c_reg[p0] + ii * g;
            c_reg[p0] = c;
            float h = o * tanh_fast(c);

            size_t idx = (size_t)b * H_ + j0 + jl;
            out_t[idx] = h;
            __nv_bfloat16 hhi = __float2bfloat16(h);
            hh_o[idx] = hhi;
            hl_o[idx] = __float2bfloat16(h - __bfloat162float(hhi));
            if (hc_tail && t == T_ - 1) {
                hc_tail[idx] = h;
                hc_tail[(size_t)BH_ + idx] = c;
            }
        }

        // grid barrier (skip after last step)
        if (t + 1 < T_) {
            __syncthreads();
            if (tid == 0) {
                asm volatile("red.release.gpu.add.u32 [%0], 1;" :: "l"(&g_bar) : "memory");
                unsigned target = (unsigned)(t + 1) * 128u;
                unsigned v;
                do {
                    asm volatile("ld.acquire.gpu.u32 %0, [%1];" : "=r"(v) : "l"(&g_bar) : "memory");
                } while (v < target);
            }
            __syncthreads();
        }
    }
}

// ---------------------------------------------------------------------------
extern "C" void kernel_launch(void* const* d_in, const int* in_sizes, int n_in,
                              void* d_out, int out_size)
{
    const float* X   = (const float*)d_in[0];
    const float* Wf  = (const float*)d_in[1];
    const float* bf  = (const float*)d_in[2];
    const float* gbf = (const float*)d_in[3];
    const float* Wi  = (const float*)d_in[4];
    const float* bi  = (const float*)d_in[5];
    const float* gbi = (const float*)d_in[6];
    const float* Wu  = (const float*)d_in[7];
    const float* bu  = (const float*)d_in[8];
    const float* gbu = (const float*)d_in[9];
    const float* Wo  = (const float*)d_in[10];
    const float* bo  = (const float*)d_in[11];
    const float* gbo = (const float*)d_in[12];

    float* out = (float*)d_out;

    float *p_zx;
    __nv_bfloat16 *p_whh, *p_whl, *p_hh, *p_hl;
    unsigned* p_bar;
    cudaGetSymbolAddress((void**)&p_zx,  g_zx);
    cudaGetSymbolAddress((void**)&p_whh, g_whh);
    cudaGetSymbolAddress((void**)&p_whl, g_whl);
    cudaGetSymbolAddress((void**)&p_hh,  g_hh);
    cudaGetSymbolAddress((void**)&p_hl,  g_hl);
    cudaGetSymbolAddress((void**)&p_bar, g_bar);

    cudaFuncSetAttribute(lstm_persist, cudaFuncAttributeMaxDynamicSharedMemorySize, SMEM_DYN_);

    // reset initial h (parity 0) and the barrier counter
    cudaMemsetAsync(p_hh, 0, sizeof(__nv_bfloat16) * BH_);
    cudaMemsetAsync(p_hl, 0, sizeof(__nv_bfloat16) * BH_);
    cudaMemsetAsync(p_bar, 0, sizeof(unsigned));

    // Phase 0: pack + split recurrent weights to bf16 hi/lo
    conv_w<<<(NG_ * H_) / 256, 256>>>(Wf, Wi, Wu, Wo, p_whh, p_whl);

    // Phase 1: all-timestep input projection (+bias), packed output columns
    dim3 g1(NG_ / 128, (T_ * B_) / 128);
    gemm_input<<<g1, 256>>>(X, Wf, Wi, Wu, Wo, bf, bi, bu, bo, p_zx);

    // Phase 2: persistent fused recurrence (all 256 steps in one kernel)
    const size_t TBH = (size_t)T_ * B_ * H_;
    const bool tails = out_size >= (int)(TBH + 2 * (size_t)BH_);
    lstm_persist<<<128, 128, SMEM_DYN_>>>(
        p_zx, p_whh, p_whl, p_hh, p_hl,
        gbf, gbi, gbu, gbo,
        out, tails ? out + TBH : nullptr);
}

// round 5
// speedup vs baseline: 4.3575x; 1.6719x over previous
#include <cuda_runtime.h>
#include <cuda_bf16.h>
#include <math.h>
#include <stdint.h>

#define T_  256
#define B_  64
#define D_  1024
#define H_  1024
#define DH_ 2048
#define NG_ 4096   /* 4 gates * H, packed n = j*4 + gate */
#define BH_ (B_ * H_)
#define M_  (T_ * B_)   /* 16384 */

// ---------------------------------------------------------------------------
// Device globals (scratch; no runtime allocation allowed)
// ---------------------------------------------------------------------------
__device__ float g_zx[(size_t)T_ * B_ * NG_];          // 256 MB: x-projection (packed cols)
__device__ __nv_bfloat16 g_whh[(size_t)NG_ * H_];      // packed Wh hi
__device__ __nv_bfloat16 g_whl[(size_t)NG_ * H_];      // packed Wh lo
__device__ __nv_bfloat16 g_wxh[(size_t)NG_ * D_];      // packed Wx hi
__device__ __nv_bfloat16 g_wxl[(size_t)NG_ * D_];      // packed Wx lo
__device__ __nv_bfloat16 g_xh[(size_t)M_ * D_];        // X hi
__device__ __nv_bfloat16 g_xl[(size_t)M_ * D_];        // X lo
__device__ __nv_bfloat16 g_hh[2][BH_];                 // h hi, double buffered
__device__ __nv_bfloat16 g_hl[2][BH_];                 // h lo
__device__ unsigned g_bar;                             // grid barrier counter

// ---------------------------------------------------------------------------
// PTX helpers (compute_103-portable)
// ---------------------------------------------------------------------------
__device__ __forceinline__ uint32_t smem_u32(const void* p) {
    uint32_t a;
    asm("{ .reg .u64 t; cvta.to.shared.u64 t, %1; cvt.u32.u64 %0, t; }" : "=r"(a) : "l"(p));
    return a;
}
__device__ __forceinline__ void cp_async16(uint32_t smem, const void* g) {
    asm volatile("cp.async.cg.shared.global [%0], [%1], 16;" :: "r"(smem), "l"(g) : "memory");
}
#define CP_COMMIT() asm volatile("cp.async.commit_group;" ::: "memory")
#define CP_WAIT(n)  asm volatile("cp.async.wait_group %0;" :: "n"(n) : "memory")

__device__ __forceinline__ void ldsm_x4(uint32_t& r0, uint32_t& r1, uint32_t& r2, uint32_t& r3,
                                        uint32_t addr) {
    asm volatile("ldmatrix.sync.aligned.m8n8.x4.shared.b16 {%0,%1,%2,%3}, [%4];"
                 : "=r"(r0), "=r"(r1), "=r"(r2), "=r"(r3) : "r"(addr));
}
__device__ __forceinline__ void mma_bf16(float* c,
                                         uint32_t a0, uint32_t a1, uint32_t a2, uint32_t a3,
                                         uint32_t b0, uint32_t b1) {
    asm volatile("mma.sync.aligned.m16n8k16.row.col.f32.bf16.bf16.f32 "
                 "{%0,%1,%2,%3}, {%4,%5,%6,%7}, {%8,%9}, {%0,%1,%2,%3};"
                 : "+f"(c[0]), "+f"(c[1]), "+f"(c[2]), "+f"(c[3])
                 : "r"(a0), "r"(a1), "r"(a2), "r"(a3), "r"(b0), "r"(b1));
}
#define SWZ(off) ((off) ^ (((off) >> 3) & 0x70))

__device__ __forceinline__ float sigf(float x) { return 1.0f / (1.0f + __expf(-x)); }
__device__ __forceinline__ float tanh_fast(float x) {
    float a = fabsf(x);
    float e = __expf(-2.0f * a);
    float t = (1.0f - e) / (1.0f + e);
    return copysignf(t, x);
}

// ---------------------------------------------------------------------------
// Phase 0a: split Wh (h-part) into packed bf16 hi/lo. Row n=(j<<2)|gate.
// ---------------------------------------------------------------------------
__global__ __launch_bounds__(256) void conv_w(
    const float* __restrict__ Wf, const float* __restrict__ Wi,
    const float* __restrict__ Wu, const float* __restrict__ Wo,
    __nv_bfloat16* __restrict__ hi, __nv_bfloat16* __restrict__ lo)
{
    size_t idx = (size_t)blockIdx.x * 256 + threadIdx.x;   // over NG_*H_
    int n = (int)(idx >> 10);
    int k = (int)(idx & 1023);
    int j = n >> 2, gate = n & 3;
    const float* W = (gate == 0) ? Wf : (gate == 1) ? Wi : (gate == 2) ? Wu : Wo;
    float w = W[(size_t)j * DH_ + D_ + k];
    __nv_bfloat16 h16 = __float2bfloat16(w);
    hi[idx] = h16;
    lo[idx] = __float2bfloat16(w - __bfloat162float(h16));
}

// Phase 0b: split Wx (x-part) into packed bf16 hi/lo. Row n=(j<<2)|gate.
__global__ __launch_bounds__(256) void conv_wx(
    const float* __restrict__ Wf, const float* __restrict__ Wi,
    const float* __restrict__ Wu, const float* __restrict__ Wo,
    __nv_bfloat16* __restrict__ hi, __nv_bfloat16* __restrict__ lo)
{
    size_t idx = (size_t)blockIdx.x * 256 + threadIdx.x;   // over NG_*D_
    int n = (int)(idx >> 10);
    int k = (int)(idx & 1023);
    int j = n >> 2, gate = n & 3;
    const float* W = (gate == 0) ? Wf : (gate == 1) ? Wi : (gate == 2) ? Wu : Wo;
    float w = W[(size_t)j * DH_ + k];
    __nv_bfloat16 h16 = __float2bfloat16(w);
    hi[idx] = h16;
    lo[idx] = __float2bfloat16(w - __bfloat162float(h16));
}

// Phase 0c: split X into bf16 hi/lo.
__global__ __launch_bounds__(256) void conv_x(
    const float* __restrict__ X,
    __nv_bfloat16* __restrict__ hi, __nv_bfloat16* __restrict__ lo)
{
    size_t idx = (size_t)blockIdx.x * 256 + threadIdx.x;   // over M_*D_
    float x = X[idx];
    __nv_bfloat16 h16 = __float2bfloat16(x);
    hi[idx] = h16;
    lo[idx] = __float2bfloat16(x - __bfloat162float(h16));
}

// ---------------------------------------------------------------------------
// Phase 1: input projection on tensor cores (split bf16).
// Z(M x NG, packed cols) = X(M x D) @ Wx^T + bias, fp32 out.
// CTA: 128x128 tile. 256 threads = 8 warps (2 in M x 4 in N).
// Warp: 64x32 via 4 m-tiles x 4 n8-frags, 3 split products.
// K chunked by 64, 2-stage cp.async double buffer.
// SMEM/stage: Ah 16K | Al 16K | Bh 16K | Bl 16K  (2 stages = 128 KB)
// ---------------------------------------------------------------------------
#define GS_(s)   ((s) * 65536)
#define GA_HI(s) (GS_(s) + 0)
#define GA_LO(s) (GS_(s) + 16384)
#define GB_HI(s) (GS_(s) + 32768)
#define GB_LO(s) (GS_(s) + 49152)
#define GSMEM_   131072

__global__ __launch_bounds__(256) void gemm_tc(
    const __nv_bfloat16* __restrict__ Xh, const __nv_bfloat16* __restrict__ Xl,
    const __nv_bfloat16* __restrict__ Wxh, const __nv_bfloat16* __restrict__ Wxl,
    const float* __restrict__ bf, const float* __restrict__ bi,
    const float* __restrict__ bu, const float* __restrict__ bo,
    float* __restrict__ Z)
{
    extern __shared__ __align__(1024) char sm[];
    __shared__ float s_bias[128];

    const uint32_t sbase = smem_u32(sm);
    const int tid  = threadIdx.x;
    const int wid  = tid >> 5;
    const int lane = tid & 31;
    const int n0   = blockIdx.x * 128;   // packed col base
    const int m0   = blockIdx.y * 128;

    const int wm = wid & 1;              // M half (64 rows)
    const int wn = wid >> 1;             // N quarter (32 cols)

    if (tid < 128) {
        int n = n0 + tid, gate = n & 3, j = n >> 2;
        const float* Ba = (gate == 0) ? bf : (gate == 1) ? bi : (gate == 2) ? bu : bo;
        s_bias[tid] = Ba[j];
    }

    const char* xh8 = (const char*)(Xh + (size_t)m0 * D_);
    const char* xl8 = (const char*)(Xl + (size_t)m0 * D_);
    const char* wh8 = (const char*)(Wxh + (size_t)n0 * D_);
    const char* wl8 = (const char*)(Wxl + (size_t)n0 * D_);

    // load chunk ch (K cols [ch*64, ch*64+64)) into stage s
    auto load_chunk = [&](int ch, int s) {
#pragma unroll
        for (int r4 = 0; r4 < 4; r4++) {         // 1024 slots = 128 rows x 8 cg
            int idx = tid + r4 * 256;
            int row = idx >> 3, cg = idx & 7;
            size_t goff = (size_t)row * 2048 + (size_t)ch * 128 + cg * 16;
            uint32_t soff = SWZ((uint32_t)(row * 128 + cg * 16));
            cp_async16(sbase + GA_HI(s) + soff, xh8 + goff);
            cp_async16(sbase + GA_LO(s) + soff, xl8 + goff);
            cp_async16(sbase + GB_HI(s) + soff, wh8 + goff);
            cp_async16(sbase + GB_LO(s) + soff, wl8 + goff);
        }
    };

    float acc[4][4][4];
#pragma unroll
    for (int mt = 0; mt < 4; mt++)
#pragma unroll
        for (int nt = 0; nt < 4; nt++)
#pragma unroll
            for (int i = 0; i < 4; i++) acc[mt][nt][i] = 0.0f;

    // lane-derived fragment addressing (proven in round 3)
    const uint32_t a_kb = (uint32_t)((lane >> 4) << 3);
    const uint32_t b_nt = (uint32_t)((lane >> 3) >> 1);
    const uint32_t b_kb = (uint32_t)(((lane >> 3) & 1) * 8);
    const uint32_t b_r  = (uint32_t)(lane & 7);

    load_chunk(0, 0);
    CP_COMMIT();

    for (int ch = 0; ch < 16; ch++) {
        const int s = ch & 1;
        if (ch + 1 < 16) {
            load_chunk(ch + 1, s ^ 1);
            CP_COMMIT();
            CP_WAIT(1);
        } else {
            CP_WAIT(0);
        }
        __syncthreads();

        const uint32_t Ah = sbase + GA_HI(s), Al = sbase + GA_LO(s);
        const uint32_t Bh = sbase + GB_HI(s), Bl = sbase + GB_LO(s);

#pragma unroll
        for (int ks = 0; ks < 4; ks++) {
            uint32_t ah[4][4], al[4][4];
#pragma unroll
            for (int mt = 0; mt < 4; mt++) {
                uint32_t row = (uint32_t)(wm * 64 + mt * 16 + (lane & 15));
                uint32_t aoff = SWZ((row << 7) + (ks * 16 + a_kb) * 2);
                ldsm_x4(ah[mt][0], ah[mt][1], ah[mt][2], ah[mt][3], Ah + aoff);
                ldsm_x4(al[mt][0], al[mt][1], al[mt][2], al[mt][3], Al + aoff);
            }
            uint32_t bh[8], bl[8];
#pragma unroll
            for (int np = 0; np < 2; np++) {
                uint32_t row = (uint32_t)(wn * 32) + (np * 2 + b_nt) * 8 + b_r;
                uint32_t boff = SWZ((row << 7) + (ks * 16 + b_kb) * 2);
                ldsm_x4(bh[np*4+0], bh[np*4+1], bh[np*4+2], bh[np*4+3], Bh + boff);
                ldsm_x4(bl[np*4+0], bl[np*4+1], bl[np*4+2], bl[np*4+3], Bl + boff);
            }
#pragma unroll
            for (int mt = 0; mt < 4; mt++)
#pragma unroll
                for (int nt = 0; nt < 4; nt++) {
                    mma_bf16(acc[mt][nt], ah[mt][0], ah[mt][1], ah[mt][2], ah[mt][3],
                             bh[nt*2], bh[nt*2+1]);
                    mma_bf16(acc[mt][nt], ah[mt][0], ah[mt][1], ah[mt][2], ah[mt][3],
                             bl[nt*2], bl[nt*2+1]);
                    mma_bf16(acc[mt][nt], al[mt][0], al[mt][1], al[mt][2], al[mt][3],
                             bh[nt*2], bh[nt*2+1]);
                }
        }
        __syncthreads();
    }

    // epilogue: add bias, write fp32 Z
    const int g  = lane >> 2;
    const int tg = lane & 3;
#pragma unroll
    for (int mt = 0; mt < 4; mt++) {
        int r0 = m0 + wm * 64 + mt * 16 + g;
#pragma unroll
        for (int nt = 0; nt < 4; nt++) {
            int nl = wn * 32 + nt * 8 + tg * 2;
            float bia0 = s_bias[nl], bia1 = s_bias[nl + 1];
            float2 v0 = make_float2(acc[mt][nt][0] + bia0, acc[mt][nt][1] + bia1);
            float2 v1 = make_float2(acc[mt][nt][2] + bia0, acc[mt][nt][3] + bia1);
            *(float2*)&Z[(size_t)r0 * NG_ + n0 + nl]       = v0;
            *(float2*)&Z[(size_t)(r0 + 8) * NG_ + n0 + nl] = v1;
        }
    }
}

// ---------------------------------------------------------------------------
// Phase 2: persistent recurrence (unchanged from round 4, passing).
// ---------------------------------------------------------------------------
#define NST_      3
#define W_HI_     0
#define W_LO_     65536
#define A_HI_(s)  (131072 + (s) * 16384)
#define A_LO_(s)  (131072 + (s) * 16384 + 8192)
#define ZX_OFF_   180224
#define ZS_OFF_   131072
#define SMEM_DYN_ 188416

__global__ __launch_bounds__(128) void lstm_persist(
    const float* __restrict__ Zx_all,
    const __nv_bfloat16* __restrict__ Whh,
    const __nv_bfloat16* __restrict__ Whl,
    __nv_bfloat16* __restrict__ hh,    // [2][BH_]
    __nv_bfloat16* __restrict__ hl,
    const float* __restrict__ gbf, const float* __restrict__ gbi,
    const float* __restrict__ gbu, const float* __restrict__ gbo,
    float* __restrict__ out,           // [T][B][H]
    float* __restrict__ hc_tail)       // null or [hx|cx]
{
    extern __shared__ __align__(1024) char sm[];
    __shared__ float s_gb[32];

    const uint32_t sbase = smem_u32(sm);
    const int tid  = threadIdx.x;
    const int wid  = tid >> 5;
    const int lane = tid & 31;
    const int bx   = blockIdx.x;
    const int j0   = bx * 8;

    if (tid < 32) {
        int gate = tid >> 3, jl = tid & 7;
        const float* gp = (gate == 0) ? gbf : (gate == 1) ? gbi : (gate == 2) ? gbu : gbo;
        s_gb[tid] = gp[j0 + jl];
    }

    {
        const char* wh8 = (const char*)(Whh + (size_t)bx * 32 * H_);
        const char* wl8 = (const char*)(Whl + (size_t)bx * 32 * H_);
        for (int i = tid; i < 4096; i += 128) {
            int c  = i >> 8;
            int r  = (i >> 3) & 31;
            int cg = i & 7;
            size_t goff = (size_t)r * 2048 + (size_t)c * 128 + cg * 16;
            uint32_t soff = (uint32_t)c * 4096 + SWZ((uint32_t)(r * 128 + cg * 16));
            cp_async16(sbase + W_HI_ + soff, wh8 + goff);
            cp_async16(sbase + W_LO_ + soff, wl8 + goff);
        }
        CP_COMMIT(); CP_WAIT(0);
        __syncthreads();
    }

    const int m0      = wid * 16;
    const uint32_t a_r  = (uint32_t)(m0 + (lane & 15));
    const uint32_t a_kb = (uint32_t)((lane >> 4) << 3);
    const uint32_t b_nt = (uint32_t)((lane >> 3) >> 1);
    const uint32_t b_kb = (uint32_t)(((lane >> 3) & 1) * 8);
    const uint32_t b_r  = (uint32_t)(lane & 7);

    float c_reg[4] = {0.f, 0.f, 0.f, 0.f};

    for (int t = 0; t < T_; t++) {
        const char* hh8 = (const char*)(hh + (size_t)(t & 1) * BH_);
        const char* hl8 = (const char*)(hl + (size_t)(t & 1) * BH_);
        __nv_bfloat16* hh_o = hh + (size_t)((t + 1) & 1) * BH_;
        __nv_bfloat16* hl_o = hl + (size_t)((t + 1) & 1) * BH_;
        const float* zx_t = Zx_all + (size_t)t * B_ * NG_;

        auto load_A = [&](int ch, int s) {
#pragma unroll
            for (int r4 = 0; r4 < 4; r4++) {
                int idx = tid + r4 * 128;
                int row = idx >> 3, cg = idx & 7;
                size_t goff = (size_t)row * 2048 + (size_t)ch * 128 + cg * 16;
                uint32_t soff = SWZ((uint32_t)(row * 128 + cg * 16));
                cp_async16(sbase + A_HI_(s) + soff, hh8 + goff);
                cp_async16(sbase + A_LO_(s) + soff, hl8 + goff);
            }
        };

#pragma unroll
        for (int r4 = 0; r4 < 4; r4++) {
            int slot = tid + r4 * 128;
            int b = slot >> 3, cg = slot & 7;
            const char* src = (const char*)(zx_t + (size_t)b * NG_ + bx * 32) + cg * 16;
            cp_async16(sbase + ZX_OFF_ + (uint32_t)(b * 128 + cg * 16), src);
        }
        load_A(0, 0); CP_COMMIT();
        load_A(1, 1); CP_COMMIT();

        float acc[4][4];
#pragma unroll
        for (int nt = 0; nt < 4; nt++)
#pragma unroll
            for (int i = 0; i < 4; i++) acc[nt][i] = 0.0f;

        for (int ch = 0; ch < 16; ch++) {
            const int s = ch % NST_;
            if (ch + 2 < 16) { load_A(ch + 2, (ch + 2) % NST_); CP_COMMIT(); CP_WAIT(2); }
            else if (ch == 14) { CP_WAIT(1); }
            else { CP_WAIT(0); }
            __syncthreads();

            const uint32_t Ah = sbase + A_HI_(s), Al = sbase + A_LO_(s);
            const uint32_t Bh = sbase + W_HI_ + (uint32_t)ch * 4096;
            const uint32_t Bl = sbase + W_LO_ + (uint32_t)ch * 4096;

#pragma unroll
            for (int ks = 0; ks < 4; ks++) {
                uint32_t aoff = SWZ((a_r << 7) + (ks * 16 + a_kb) * 2);
                uint32_t ah0, ah1, ah2, ah3, al0, al1, al2, al3;
                ldsm_x4(ah0, ah1, ah2, ah3, Ah + aoff);
                ldsm_x4(al0, al1, al2, al3, Al + aoff);

                uint32_t bh[8], bl[8];
#pragma unroll
                for (int np = 0; np < 2; np++) {
                    uint32_t row = (np * 2 + b_nt) * 8 + b_r;
                    uint32_t boff = SWZ((row << 7) + (ks * 16 + b_kb) * 2);
                    ldsm_x4(bh[np*4+0], bh[np*4+1], bh[np*4+2], bh[np*4+3], Bh + boff);
                    ldsm_x4(bl[np*4+0], bl[np*4+1], bl[np*4+2], bl[np*4+3], Bl + boff);
                }
#pragma unroll
                for (int nt = 0; nt < 4; nt++) {
                    mma_bf16(acc[nt], ah0, ah1, ah2, ah3, bh[nt*2], bh[nt*2+1]);
                    mma_bf16(acc[nt], ah0, ah1, ah2, ah3, bl[nt*2], bl[nt*2+1]);
                    mma_bf16(acc[nt], al0, al1, al2, al3, bh[nt*2], bh[nt*2+1]);
                }
            }
            __syncthreads();
        }

        float* Zs = (float*)(sm + ZS_OFF_);
        {
            const int g  = lane >> 2;
            const int tg = lane & 3;
#pragma unroll
            for (int nt = 0; nt < 4; nt++) {
                int n = nt * 8 + tg * 2;
                Zs[(m0 + g)     * 32 + n]     = acc[nt][0];
                Zs[(m0 + g)     * 32 + n + 1] = acc[nt][1];
                Zs[(m0 + g + 8) * 32 + n]     = acc[nt][2];
                Zs[(m0 + g + 8) * 32 + n + 1] = acc[nt][3];
            }
        }
        __syncthreads();

        const float* zxs = (const float*)(sm + ZX_OFF_);
        float* out_t = out + (size_t)t * BH_;
#pragma unroll
        for (int p0 = 0; p0 < 4; p0++) {
            int p  = tid + p0 * 128;
            int b  = p >> 3;
            int jl = p & 7;
            float4 zh  = *(const float4*)&Zs[b * 32 + jl * 4];
            float4 zx4 = *(const float4*)&zxs[b * 32 + jl * 4];

            float f  = sigf(__cosf(zh.x + zx4.x) + s_gb[0 * 8 + jl]);
            float ii = sigf(__cosf(zh.y + zx4.y) + s_gb[1 * 8 + jl]);
            float g  = tanh_fast(__cosf(zh.z + zx4.z) + s_gb[2 * 8 + jl]);
            float o  = sigf(__cosf(zh.w + zx4.w) + s_gb[3 * 8 + jl]);

            float c = f * c_reg[p0] + ii * g;
            c_reg[p0] = c;
            float h = o * tanh_fast(c);

            size_t idx = (size_t)b * H_ + j0 + jl;
            out_t[idx] = h;
            __nv_bfloat16 hhi = __float2bfloat16(h);
            hh_o[idx] = hhi;
            hl_o[idx] = __float2bfloat16(h - __bfloat162float(hhi));
            if (hc_tail && t == T_ - 1) {
                hc_tail[idx] = h;
                hc_tail[(size_t)BH_ + idx] = c;
            }
        }

        if (t + 1 < T_) {
            __syncthreads();
            if (tid == 0) {
                asm volatile("red.release.gpu.add.u32 [%0], 1;" :: "l"(&g_bar) : "memory");
                unsigned target = (unsigned)(t + 1) * 128u;
                unsigned v;
                do {
                    asm volatile("ld.acquire.gpu.u32 %0, [%1];" : "=r"(v) : "l"(&g_bar) : "memory");
                } while (v < target);
            }
            __syncthreads();
        }
    }
}

// ---------------------------------------------------------------------------
extern "C" void kernel_launch(void* const* d_in, const int* in_sizes, int n_in,
                              void* d_out, int out_size)
{
    const float* X   = (const float*)d_in[0];
    const float* Wf  = (const float*)d_in[1];
    const float* bf  = (const float*)d_in[2];
    const float* gbf = (const float*)d_in[3];
    const float* Wi  = (const float*)d_in[4];
    const float* bi  = (const float*)d_in[5];
    const float* gbi = (const float*)d_in[6];
    const float* Wu  = (const float*)d_in[7];
    const float* bu  = (const float*)d_in[8];
    const float* gbu = (const float*)d_in[9];
    const float* Wo  = (const float*)d_in[10];
    const float* bo  = (const float*)d_in[11];
    const float* gbo = (const float*)d_in[12];

    float* out = (float*)d_out;

    float *p_zx;
    __nv_bfloat16 *p_whh, *p_whl, *p_wxh, *p_wxl, *p_xh, *p_xl, *p_hh, *p_hl;
    unsigned* p_bar;
    cudaGetSymbolAddress((void**)&p_zx,  g_zx);
    cudaGetSymbolAddress((void**)&p_whh, g_whh);
    cudaGetSymbolAddress((void**)&p_whl, g_whl);
    cudaGetSymbolAddress((void**)&p_wxh, g_wxh);
    cudaGetSymbolAddress((void**)&p_wxl, g_wxl);
    cudaGetSymbolAddress((void**)&p_xh,  g_xh);
    cudaGetSymbolAddress((void**)&p_xl,  g_xl);
    cudaGetSymbolAddress((void**)&p_hh,  g_hh);
    cudaGetSymbolAddress((void**)&p_hl,  g_hl);
    cudaGetSymbolAddress((void**)&p_bar, g_bar);

    cudaFuncSetAttribute(lstm_persist, cudaFuncAttributeMaxDynamicSharedMemorySize, SMEM_DYN_);
    cudaFuncSetAttribute(gemm_tc, cudaFuncAttributeMaxDynamicSharedMemorySize, GSMEM_);

    // reset initial h (parity 0) and the barrier counter
    cudaMemsetAsync(p_hh, 0, sizeof(__nv_bfloat16) * BH_);
    cudaMemsetAsync(p_hl, 0, sizeof(__nv_bfloat16) * BH_);
    cudaMemsetAsync(p_bar, 0, sizeof(unsigned));

    // Phase 0: split weights and inputs to bf16 hi/lo
    conv_w<<<(NG_ * H_) / 256, 256>>>(Wf, Wi, Wu, Wo, p_whh, p_whl);
    conv_wx<<<(NG_ * D_) / 256, 256>>>(Wf, Wi, Wu, Wo, p_wxh, p_wxl);
    conv_x<<<(M_ * D_) / 256, 256>>>(X, p_xh, p_xl);

    // Phase 1: all-timestep input projection (+bias) on tensor cores
    dim3 g1(NG_ / 128, M_ / 128);
    gemm_tc<<<g1, 256, GSMEM_>>>(p_xh, p_xl, p_wxh, p_wxl, bf, bi, bu, bo, p_zx);

    // Phase 2: persistent fused recurrence (all 256 steps in one kernel)
    const size_t TBH = (size_t)T_ * B_ * H_;
    const bool tails = out_size >= (int)(TBH + 2 * (size_t)BH_);
    lstm_persist<<<128, 128, SMEM_DYN_>>>(
        p_zx, p_whh, p_whl, p_hh, p_hl,
        gbf, gbi, gbu, gbo,
        out, tails ? out + TBH : nullptr);
}

// round 6
// speedup vs baseline: 4.5923x; 1.0539x over previous
#include <cuda_runtime.h>
#include <cuda_bf16.h>
#include <math.h>
#include <stdint.h>

#define T_  256
#define B_  64
#define D_  1024
#define H_  1024
#define DH_ 2048
#define NG_ 4096   /* 4 gates * H, packed n = j*4 + gate */
#define BH_ (B_ * H_)
#define M_  (T_ * B_)   /* 16384 */

// ---------------------------------------------------------------------------
// Device globals (scratch; no runtime allocation allowed)
// ---------------------------------------------------------------------------
__device__ float g_zx[(size_t)T_ * B_ * NG_];          // 256 MB: x-projection (packed cols)
__device__ __nv_bfloat16 g_whh[(size_t)NG_ * H_];      // packed Wh hi
__device__ __nv_bfloat16 g_whl[(size_t)NG_ * H_];      // packed Wh lo
__device__ __nv_bfloat16 g_wxh[(size_t)NG_ * D_];      // packed Wx hi
__device__ __nv_bfloat16 g_wxl[(size_t)NG_ * D_];      // packed Wx lo
__device__ __nv_bfloat16 g_xh[(size_t)M_ * D_];        // X hi
__device__ __nv_bfloat16 g_xl[(size_t)M_ * D_];        // X lo
__device__ __nv_bfloat16 g_hh[2][BH_];                 // h hi, double buffered
__device__ __nv_bfloat16 g_hl[2][BH_];                 // h lo
__device__ unsigned g_bar;                             // grid barrier counter

// ---------------------------------------------------------------------------
// PTX helpers (compute_103-portable)
// ---------------------------------------------------------------------------
__device__ __forceinline__ uint32_t smem_u32(const void* p) {
    uint32_t a;
    asm("{ .reg .u64 t; cvta.to.shared.u64 t, %1; cvt.u32.u64 %0, t; }" : "=r"(a) : "l"(p));
    return a;
}
__device__ __forceinline__ void cp_async16(uint32_t smem, const void* g) {
    asm volatile("cp.async.cg.shared.global [%0], [%1], 16;" :: "r"(smem), "l"(g) : "memory");
}
#define CP_COMMIT() asm volatile("cp.async.commit_group;" ::: "memory")
#define CP_WAIT(n)  asm volatile("cp.async.wait_group %0;" :: "n"(n) : "memory")

__device__ __forceinline__ void ldsm_x4(uint32_t& r0, uint32_t& r1, uint32_t& r2, uint32_t& r3,
                                        uint32_t addr) {
    asm volatile("ldmatrix.sync.aligned.m8n8.x4.shared.b16 {%0,%1,%2,%3}, [%4];"
                 : "=r"(r0), "=r"(r1), "=r"(r2), "=r"(r3) : "r"(addr));
}
__device__ __forceinline__ void mma_bf16(float* c,
                                         uint32_t a0, uint32_t a1, uint32_t a2, uint32_t a3,
                                         uint32_t b0, uint32_t b1) {
    asm volatile("mma.sync.aligned.m16n8k16.row.col.f32.bf16.bf16.f32 "
                 "{%0,%1,%2,%3}, {%4,%5,%6,%7}, {%8,%9}, {%0,%1,%2,%3};"
                 : "+f"(c[0]), "+f"(c[1]), "+f"(c[2]), "+f"(c[3])
                 : "r"(a0), "r"(a1), "r"(a2), "r"(a3), "r"(b0), "r"(b1));
}
#define SWZ(off) ((off) ^ (((off) >> 3) & 0x70))

__device__ __forceinline__ float sigf(float x) { return 1.0f / (1.0f + __expf(-x)); }
__device__ __forceinline__ float tanh_fast(float x) {
    float a = fabsf(x);
    float e = __expf(-2.0f * a);
    float t = (1.0f - e) / (1.0f + e);
    return copysignf(t, x);
}

// ---------------------------------------------------------------------------
// Phase 0a: split Wh (h-part) into packed bf16 hi/lo. Row n=(j<<2)|gate.
// ---------------------------------------------------------------------------
__global__ __launch_bounds__(256) void conv_w(
    const float* __restrict__ Wf, const float* __restrict__ Wi,
    const float* __restrict__ Wu, const float* __restrict__ Wo,
    __nv_bfloat16* __restrict__ hi, __nv_bfloat16* __restrict__ lo)
{
    size_t idx = (size_t)blockIdx.x * 256 + threadIdx.x;   // over NG_*H_
    int n = (int)(idx >> 10);
    int k = (int)(idx & 1023);
    int j = n >> 2, gate = n & 3;
    const float* W = (gate == 0) ? Wf : (gate == 1) ? Wi : (gate == 2) ? Wu : Wo;
    float w = W[(size_t)j * DH_ + D_ + k];
    __nv_bfloat16 h16 = __float2bfloat16(w);
    hi[idx] = h16;
    lo[idx] = __float2bfloat16(w - __bfloat162float(h16));
}

// Phase 0b: split Wx (x-part) into packed bf16 hi/lo. Row n=(j<<2)|gate.
__global__ __launch_bounds__(256) void conv_wx(
    const float* __restrict__ Wf, const float* __restrict__ Wi,
    const float* __restrict__ Wu, const float* __restrict__ Wo,
    __nv_bfloat16* __restrict__ hi, __nv_bfloat16* __restrict__ lo)
{
    size_t idx = (size_t)blockIdx.x * 256 + threadIdx.x;   // over NG_*D_
    int n = (int)(idx >> 10);
    int k = (int)(idx & 1023);
    int j = n >> 2, gate = n & 3;
    const float* W = (gate == 0) ? Wf : (gate == 1) ? Wi : (gate == 2) ? Wu : Wo;
    float w = W[(size_t)j * DH_ + k];
    __nv_bfloat16 h16 = __float2bfloat16(w);
    hi[idx] = h16;
    lo[idx] = __float2bfloat16(w - __bfloat162float(h16));
}

// Phase 0c: split X into bf16 hi/lo.
__global__ __launch_bounds__(256) void conv_x(
    const float* __restrict__ X,
    __nv_bfloat16* __restrict__ hi, __nv_bfloat16* __restrict__ lo)
{
    size_t idx = (size_t)blockIdx.x * 256 + threadIdx.x;   // over M_*D_
    float x = X[idx];
    __nv_bfloat16 h16 = __float2bfloat16(x);
    hi[idx] = h16;
    lo[idx] = __float2bfloat16(x - __bfloat162float(h16));
}

// ---------------------------------------------------------------------------
// Phase 1: input projection on tensor cores (split bf16). Unchanged from R5.
// ---------------------------------------------------------------------------
#define GS_(s)   ((s) * 65536)
#define GA_HI(s) (GS_(s) + 0)
#define GA_LO(s) (GS_(s) + 16384)
#define GB_HI(s) (GS_(s) + 32768)
#define GB_LO(s) (GS_(s) + 49152)
#define GSMEM_   131072

__global__ __launch_bounds__(256) void gemm_tc(
    const __nv_bfloat16* __restrict__ Xh, const __nv_bfloat16* __restrict__ Xl,
    const __nv_bfloat16* __restrict__ Wxh, const __nv_bfloat16* __restrict__ Wxl,
    const float* __restrict__ bf, const float* __restrict__ bi,
    const float* __restrict__ bu, const float* __restrict__ bo,
    float* __restrict__ Z)
{
    extern __shared__ __align__(1024) char sm[];
    __shared__ float s_bias[128];

    const uint32_t sbase = smem_u32(sm);
    const int tid  = threadIdx.x;
    const int wid  = tid >> 5;
    const int lane = tid & 31;
    const int n0   = blockIdx.x * 128;   // packed col base
    const int m0   = blockIdx.y * 128;

    const int wm = wid & 1;              // M half (64 rows)
    const int wn = wid >> 1;             // N quarter (32 cols)

    if (tid < 128) {
        int n = n0 + tid, gate = n & 3, j = n >> 2;
        const float* Ba = (gate == 0) ? bf : (gate == 1) ? bi : (gate == 2) ? bu : bo;
        s_bias[tid] = Ba[j];
    }

    const char* xh8 = (const char*)(Xh + (size_t)m0 * D_);
    const char* xl8 = (const char*)(Xl + (size_t)m0 * D_);
    const char* wh8 = (const char*)(Wxh + (size_t)n0 * D_);
    const char* wl8 = (const char*)(Wxl + (size_t)n0 * D_);

    auto load_chunk = [&](int ch, int s) {
#pragma unroll
        for (int r4 = 0; r4 < 4; r4++) {
            int idx = tid + r4 * 256;
            int row = idx >> 3, cg = idx & 7;
            size_t goff = (size_t)row * 2048 + (size_t)ch * 128 + cg * 16;
            uint32_t soff = SWZ((uint32_t)(row * 128 + cg * 16));
            cp_async16(sbase + GA_HI(s) + soff, xh8 + goff);
            cp_async16(sbase + GA_LO(s) + soff, xl8 + goff);
            cp_async16(sbase + GB_HI(s) + soff, wh8 + goff);
            cp_async16(sbase + GB_LO(s) + soff, wl8 + goff);
        }
    };

    float acc[4][4][4];
#pragma unroll
    for (int mt = 0; mt < 4; mt++)
#pragma unroll
        for (int nt = 0; nt < 4; nt++)
#pragma unroll
            for (int i = 0; i < 4; i++) acc[mt][nt][i] = 0.0f;

    const uint32_t a_kb = (uint32_t)((lane >> 4) << 3);
    const uint32_t b_nt = (uint32_t)((lane >> 3) >> 1);
    const uint32_t b_kb = (uint32_t)(((lane >> 3) & 1) * 8);
    const uint32_t b_r  = (uint32_t)(lane & 7);

    load_chunk(0, 0);
    CP_COMMIT();

    for (int ch = 0; ch < 16; ch++) {
        const int s = ch & 1;
        if (ch + 1 < 16) {
            load_chunk(ch + 1, s ^ 1);
            CP_COMMIT();
            CP_WAIT(1);
        } else {
            CP_WAIT(0);
        }
        __syncthreads();

        const uint32_t Ah = sbase + GA_HI(s), Al = sbase + GA_LO(s);
        const uint32_t Bh = sbase + GB_HI(s), Bl = sbase + GB_LO(s);

#pragma unroll
        for (int ks = 0; ks < 4; ks++) {
            uint32_t ah[4][4], al[4][4];
#pragma unroll
            for (int mt = 0; mt < 4; mt++) {
                uint32_t row = (uint32_t)(wm * 64 + mt * 16 + (lane & 15));
                uint32_t aoff = SWZ((row << 7) + (ks * 16 + a_kb) * 2);
                ldsm_x4(ah[mt][0], ah[mt][1], ah[mt][2], ah[mt][3], Ah + aoff);
                ldsm_x4(al[mt][0], al[mt][1], al[mt][2], al[mt][3], Al + aoff);
            }
            uint32_t bh[8], bl[8];
#pragma unroll
            for (int np = 0; np < 2; np++) {
                uint32_t row = (uint32_t)(wn * 32) + (np * 2 + b_nt) * 8 + b_r;
                uint32_t boff = SWZ((row << 7) + (ks * 16 + b_kb) * 2);
                ldsm_x4(bh[np*4+0], bh[np*4+1], bh[np*4+2], bh[np*4+3], Bh + boff);
                ldsm_x4(bl[np*4+0], bl[np*4+1], bl[np*4+2], bl[np*4+3], Bl + boff);
            }
#pragma unroll
            for (int mt = 0; mt < 4; mt++)
#pragma unroll
                for (int nt = 0; nt < 4; nt++) {
                    mma_bf16(acc[mt][nt], ah[mt][0], ah[mt][1], ah[mt][2], ah[mt][3],
                             bh[nt*2], bh[nt*2+1]);
                    mma_bf16(acc[mt][nt], ah[mt][0], ah[mt][1], ah[mt][2], ah[mt][3],
                             bl[nt*2], bl[nt*2+1]);
                    mma_bf16(acc[mt][nt], al[mt][0], al[mt][1], al[mt][2], al[mt][3],
                             bh[nt*2], bh[nt*2+1]);
                }
        }
        __syncthreads();
    }

    const int g  = lane >> 2;
    const int tg = lane & 3;
#pragma unroll
    for (int mt = 0; mt < 4; mt++) {
        int r0 = m0 + wm * 64 + mt * 16 + g;
#pragma unroll
        for (int nt = 0; nt < 4; nt++) {
            int nl = wn * 32 + nt * 8 + tg * 2;
            float bia0 = s_bias[nl], bia1 = s_bias[nl + 1];
            float2 v0 = make_float2(acc[mt][nt][0] + bia0, acc[mt][nt][1] + bia1);
            float2 v1 = make_float2(acc[mt][nt][2] + bia0, acc[mt][nt][3] + bia1);
            *(float2*)&Z[(size_t)r0 * NG_ + n0 + nl]       = v0;
            *(float2*)&Z[(size_t)(r0 + 8) * NG_ + n0 + nl] = v1;
        }
    }
}

// ---------------------------------------------------------------------------
// Phase 2: persistent recurrence v2. 128 CTAs, 256 threads (8 warps).
// Warp grid: wm in 0..3 (16 batch rows), wn in 0..1 (16 packed cols).
// K chunked by 128 (2 x 64-col sub-tiles), 2-stage cp.async pipeline.
// SMEM: W_hi 64K @0 | W_lo 64K @64K | A stages 2x32K @128K | ZX 8K @192K
//   per A stage: [hi sub0 8K][hi sub1 8K][lo sub0 8K][lo sub1 8K]
// Zs epilogue overlays A stage 0.
// ---------------------------------------------------------------------------
#define W_HI_     0
#define W_LO_     65536
#define AST_(s)   (131072 + (s) * 32768)
#define ZX_OFF_   196608
#define ZS_OFF_   131072
#define SMEM_DYN_ 204800

__global__ __launch_bounds__(256) void lstm_persist(
    const float* __restrict__ Zx_all,
    const __nv_bfloat16* __restrict__ Whh,
    const __nv_bfloat16* __restrict__ Whl,
    __nv_bfloat16* __restrict__ hh,    // [2][BH_]
    __nv_bfloat16* __restrict__ hl,
    const float* __restrict__ gbf, const float* __restrict__ gbi,
    const float* __restrict__ gbu, const float* __restrict__ gbo,
    float* __restrict__ out,           // [T][B][H]
    float* __restrict__ hc_tail)       // null or [hx|cx]
{
    extern __shared__ __align__(1024) char sm[];
    __shared__ float s_gb[32];

    const uint32_t sbase = smem_u32(sm);
    const int tid  = threadIdx.x;
    const int wid  = tid >> 5;
    const int lane = tid & 31;
    const int bx   = blockIdx.x;
    const int j0   = bx * 8;

    if (tid < 32) {
        int gate = tid >> 3, jl = tid & 7;
        const float* gp = (gate == 0) ? gbf : (gate == 1) ? gbi : (gate == 2) ? gbu : gbo;
        s_gb[tid] = gp[j0 + jl];
    }

    // ---- resident weights: 32 rows x 1024 k x (hi+lo), 64-col chunk layout ----
    {
        const char* wh8 = (const char*)(Whh + (size_t)bx * 32 * H_);
        const char* wl8 = (const char*)(Whl + (size_t)bx * 32 * H_);
        for (int i = tid; i < 4096; i += 256) {   // 16 c64 * 32 rows * 8 cg
            int c  = i >> 8;
            int r  = (i >> 3) & 31;
            int cg = i & 7;
            size_t goff = (size_t)r * 2048 + (size_t)c * 128 + cg * 16;
            uint32_t soff = (uint32_t)c * 4096 + SWZ((uint32_t)(r * 128 + cg * 16));
            cp_async16(sbase + W_HI_ + soff, wh8 + goff);
            cp_async16(sbase + W_LO_ + soff, wl8 + goff);
        }
        CP_COMMIT(); CP_WAIT(0);
        __syncthreads();
    }

    const int wm = wid & 3;              // 16-row batch group
    const int wn = wid >> 2;             // 16-col half
    const int m0 = wm * 16;

    const uint32_t a_r  = (uint32_t)(m0 + (lane & 15));
    const uint32_t a_kb = (uint32_t)((lane >> 4) << 3);
    const uint32_t b_nt = (uint32_t)((lane >> 3) >> 1);
    const uint32_t b_kb = (uint32_t)(((lane >> 3) & 1) * 8);
    const uint32_t b_r  = (uint32_t)(lane & 7);
    const uint32_t b_row = (uint32_t)(wn * 16) + b_nt * 8 + b_r;

    float c_reg[2] = {0.f, 0.f};

    for (int t = 0; t < T_; t++) {
        const char* hh8 = (const char*)(hh + (size_t)(t & 1) * BH_);
        const char* hl8 = (const char*)(hl + (size_t)(t & 1) * BH_);
        __nv_bfloat16* hh_o = hh + (size_t)((t + 1) & 1) * BH_;
        __nv_bfloat16* hl_o = hl + (size_t)((t + 1) & 1) * BH_;
        const float* zx_t = Zx_all + (size_t)t * B_ * NG_;

        // load 128-col chunk ch into stage s
        auto load_A = [&](int ch, int s) {
#pragma unroll
            for (int sub = 0; sub < 2; sub++) {
                int c64 = ch * 2 + sub;
#pragma unroll
                for (int r4 = 0; r4 < 2; r4++) {
                    int idx = tid + r4 * 256;           // 0..511
                    int row = idx >> 3, cg = idx & 7;
                    size_t goff = (size_t)row * 2048 + (size_t)c64 * 128 + cg * 16;
                    uint32_t soff = SWZ((uint32_t)(row * 128 + cg * 16));
                    cp_async16(sbase + AST_(s) + sub * 8192 + soff, hh8 + goff);
                    cp_async16(sbase + AST_(s) + 16384 + sub * 8192 + soff, hl8 + goff);
                }
            }
        };

        // prologue: ZX slab + chunk0 in group0
#pragma unroll
        for (int r4 = 0; r4 < 2; r4++) {
            int slot = tid + r4 * 256;       // 512 = 64 b * 8 cg
            int b = slot >> 3, cg = slot & 7;
            const char* src = (const char*)(zx_t + (size_t)b * NG_ + bx * 32) + cg * 16;
            cp_async16(sbase + ZX_OFF_ + (uint32_t)(b * 128 + cg * 16), src);
        }
        load_A(0, 0); CP_COMMIT();

        float acc[2][4];
#pragma unroll
        for (int nt = 0; nt < 2; nt++)
#pragma unroll
            for (int i = 0; i < 4; i++) acc[nt][i] = 0.0f;

        for (int ch = 0; ch < 8; ch++) {
            const int s = ch & 1;
            if (ch + 1 < 8) { load_A(ch + 1, s ^ 1); CP_COMMIT(); CP_WAIT(1); }
            else { CP_WAIT(0); }
            __syncthreads();

#pragma unroll
            for (int sub = 0; sub < 2; sub++) {
                const int c64 = ch * 2 + sub;
                const uint32_t Ah = sbase + AST_(s) + sub * 8192;
                const uint32_t Al = Ah + 16384;
                const uint32_t Bh = sbase + W_HI_ + (uint32_t)c64 * 4096;
                const uint32_t Bl = sbase + W_LO_ + (uint32_t)c64 * 4096;

#pragma unroll
                for (int ks = 0; ks < 4; ks++) {
                    uint32_t aoff = SWZ((a_r << 7) + (ks * 16 + a_kb) * 2);
                    uint32_t ah0, ah1, ah2, ah3, al0, al1, al2, al3;
                    ldsm_x4(ah0, ah1, ah2, ah3, Ah + aoff);
                    ldsm_x4(al0, al1, al2, al3, Al + aoff);

                    uint32_t boff = SWZ((b_row << 7) + (ks * 16 + b_kb) * 2);
                    uint32_t bh0, bh1, bh2, bh3, bl0, bl1, bl2, bl3;
                    ldsm_x4(bh0, bh1, bh2, bh3, Bh + boff);
                    ldsm_x4(bl0, bl1, bl2, bl3, Bl + boff);

                    mma_bf16(acc[0], ah0, ah1, ah2, ah3, bh0, bh1);
                    mma_bf16(acc[0], ah0, ah1, ah2, ah3, bl0, bl1);
                    mma_bf16(acc[0], al0, al1, al2, al3, bh0, bh1);
                    mma_bf16(acc[1], ah0, ah1, ah2, ah3, bh2, bh3);
                    mma_bf16(acc[1], ah0, ah1, ah2, ah3, bl2, bl3);
                    mma_bf16(acc[1], al0, al1, al2, al3, bh2, bh3);
                }
            }
            __syncthreads();
        }

        // stage accumulators to SMEM (overlay A stage 0)
        float* Zs = (float*)(sm + ZS_OFF_);
        {
            const int g  = lane >> 2;
            const int tg = lane & 3;
#pragma unroll
            for (int nt = 0; nt < 2; nt++) {
                int n = wn * 16 + nt * 8 + tg * 2;
                Zs[(m0 + g)     * 32 + n]     = acc[nt][0];
                Zs[(m0 + g)     * 32 + n + 1] = acc[nt][1];
                Zs[(m0 + g + 8) * 32 + n]     = acc[nt][2];
                Zs[(m0 + g + 8) * 32 + n + 1] = acc[nt][3];
            }
        }
        __syncthreads();

        // fused LSTM epilogue: 512 (b, jl) pairs, 2 per thread, c in registers
        const float* zxs = (const float*)(sm + ZX_OFF_);
        float* out_t = out + (size_t)t * BH_;
#pragma unroll
        for (int p0 = 0; p0 < 2; p0++) {
            int p  = tid + p0 * 256;
            int b  = p >> 3;
            int jl = p & 7;
            float4 zh  = *(const float4*)&Zs[b * 32 + jl * 4];
            float4 zx4 = *(const float4*)&zxs[b * 32 + jl * 4];

            float f  = sigf(__cosf(zh.x + zx4.x) + s_gb[0 * 8 + jl]);
            float ii = sigf(__cosf(zh.y + zx4.y) + s_gb[1 * 8 + jl]);
            float g  = tanh_fast(__cosf(zh.z + zx4.z) + s_gb[2 * 8 + jl]);
            float o  = sigf(__cosf(zh.w + zx4.w) + s_gb[3 * 8 + jl]);

            float c = f * c_reg[p0] + ii * g;
            c_reg[p0] = c;
            float h = o * tanh_fast(c);

            size_t idx = (size_t)b * H_ + j0 + jl;
            out_t[idx] = h;
            __nv_bfloat16 hhi = __float2bfloat16(h);
            hh_o[idx] = hhi;
            hl_o[idx] = __float2bfloat16(h - __bfloat162float(hhi));
            if (hc_tail && t == T_ - 1) {
                hc_tail[idx] = h;
                hc_tail[(size_t)BH_ + idx] = c;
            }
        }

        // grid barrier (skip after last step)
        if (t + 1 < T_) {
            __syncthreads();
            if (tid == 0) {
                asm volatile("red.release.gpu.add.u32 [%0], 1;" :: "l"(&g_bar) : "memory");
                unsigned target = (unsigned)(t + 1) * 128u;
                unsigned v;
                do {
                    asm volatile("ld.acquire.gpu.u32 %0, [%1];" : "=r"(v) : "l"(&g_bar) : "memory");
                } while (v < target);
            }
            __syncthreads();
        }
    }
}

// ---------------------------------------------------------------------------
extern "C" void kernel_launch(void* const* d_in, const int* in_sizes, int n_in,
                              void* d_out, int out_size)
{
    const float* X   = (const float*)d_in[0];
    const float* Wf  = (const float*)d_in[1];
    const float* bf  = (const float*)d_in[2];
    const float* gbf = (const float*)d_in[3];
    const float* Wi  = (const float*)d_in[4];
    const float* bi  = (const float*)d_in[5];
    const float* gbi = (const float*)d_in[6];
    const float* Wu  = (const float*)d_in[7];
    const float* bu  = (const float*)d_in[8];
    const float* gbu = (const float*)d_in[9];
    const float* Wo  = (const float*)d_in[10];
    const float* bo  = (const float*)d_in[11];
    const float* gbo = (const float*)d_in[12];

    float* out = (float*)d_out;

    float *p_zx;
    __nv_bfloat16 *p_whh, *p_whl, *p_wxh, *p_wxl, *p_xh, *p_xl, *p_hh, *p_hl;
    unsigned* p_bar;
    cudaGetSymbolAddress((void**)&p_zx,  g_zx);
    cudaGetSymbolAddress((void**)&p_whh, g_whh);
    cudaGetSymbolAddress((void**)&p_whl, g_whl);
    cudaGetSymbolAddress((void**)&p_wxh, g_wxh);
    cudaGetSymbolAddress((void**)&p_wxl, g_wxl);
    cudaGetSymbolAddress((void**)&p_xh,  g_xh);
    cudaGetSymbolAddress((void**)&p_xl,  g_xl);
    cudaGetSymbolAddress((void**)&p_hh,  g_hh);
    cudaGetSymbolAddress((void**)&p_hl,  g_hl);
    cudaGetSymbolAddress((void**)&p_bar, g_bar);

    cudaFuncSetAttribute(lstm_persist, cudaFuncAttributeMaxDynamicSharedMemorySize, SMEM_DYN_);
    cudaFuncSetAttribute(gemm_tc, cudaFuncAttributeMaxDynamicSharedMemorySize, GSMEM_);

    // reset initial h (parity 0) and the barrier counter
    cudaMemsetAsync(p_hh, 0, sizeof(__nv_bfloat16) * BH_);
    cudaMemsetAsync(p_hl, 0, sizeof(__nv_bfloat16) * BH_);
    cudaMemsetAsync(p_bar, 0, sizeof(unsigned));

    // Phase 0: split weights and inputs to bf16 hi/lo
    conv_w<<<(NG_ * H_) / 256, 256>>>(Wf, Wi, Wu, Wo, p_whh, p_whl);
    conv_wx<<<(NG_ * D_) / 256, 256>>>(Wf, Wi, Wu, Wo, p_wxh, p_wxl);
    conv_x<<<(M_ * D_) / 256, 256>>>(X, p_xh, p_xl);

    // Phase 1: all-timestep input projection (+bias) on tensor cores
    dim3 g1(NG_ / 128, M_ / 128);
    gemm_tc<<<g1, 256, GSMEM_>>>(p_xh, p_xl, p_wxh, p_wxl, bf, bi, bu, bo, p_zx);

    // Phase 2: persistent fused recurrence (all 256 steps in one kernel)
    const size_t TBH = (size_t)T_ * B_ * H_;
    const bool tails = out_size >= (int)(TBH + 2 * (size_t)BH_);
    lstm_persist<<<128, 256, SMEM_DYN_>>>(
        p_zx, p_whh, p_whl, p_hh, p_hl,
        gbf, gbi, gbu, gbo,
        out, tails ? out + TBH : nullptr);
}

// round 7
// speedup vs baseline: 4.8448x; 1.0550x over previous
#include <cuda_runtime.h>
#include <cuda_bf16.h>
#include <math.h>
#include <stdint.h>

#define T_  256
#define B_  64
#define D_  1024
#define H_  1024
#define DH_ 2048
#define NG_ 4096   /* 4 gates * H, packed n = j*4 + gate */
#define BH_ (B_ * H_)
#define M_  (T_ * B_)   /* 16384 */

// ---------------------------------------------------------------------------
// Device globals (scratch; no runtime allocation allowed)
// ---------------------------------------------------------------------------
// Zx in per-CTA slabs: [t][grp=0..127][64 b x 32 cols] fp32, slab = 8KB contiguous
__device__ float g_zx[(size_t)T_ * B_ * NG_];
__device__ __nv_bfloat16 g_whh[(size_t)NG_ * H_];      // packed Wh hi
__device__ __nv_bfloat16 g_whl[(size_t)NG_ * H_];      // packed Wh lo
__device__ __nv_bfloat16 g_wxh[(size_t)NG_ * D_];      // packed Wx hi
__device__ __nv_bfloat16 g_wxl[(size_t)NG_ * D_];      // packed Wx lo
__device__ __nv_bfloat16 g_xh[(size_t)M_ * D_];        // X hi
__device__ __nv_bfloat16 g_xl[(size_t)M_ * D_];        // X lo
// h double buffer, pre-swizzled chunk-major: [buf][hi/lo][c64 0..15][8192 B]
// within chunk: byte off = SWZ(b*128 + (k&63)*2)
__device__ __align__(128) char g_hsw[2][2][16][8192];
__device__ unsigned g_bar;                             // grid barrier counter

#define HBUF_STRIDE_ 262144   /* 2*16*8192 */
#define HHALF_STRIDE_ 131072  /* 16*8192 */

// ---------------------------------------------------------------------------
// PTX helpers (compute_103-portable)
// ---------------------------------------------------------------------------
__device__ __forceinline__ uint32_t smem_u32(const void* p) {
    uint32_t a;
    asm("{ .reg .u64 t; cvta.to.shared.u64 t, %1; cvt.u32.u64 %0, t; }" : "=r"(a) : "l"(p));
    return a;
}
__device__ __forceinline__ void cp_async16(uint32_t smem, const void* g) {
    asm volatile("cp.async.cg.shared.global [%0], [%1], 16;" :: "r"(smem), "l"(g) : "memory");
}
#define CP_COMMIT() asm volatile("cp.async.commit_group;" ::: "memory")
#define CP_WAIT(n)  asm volatile("cp.async.wait_group %0;" :: "n"(n) : "memory")

// 1D bulk copy global->shared with mbarrier completion (sm_90+, portable)
__device__ __forceinline__ void cp_bulk(uint32_t dst, const void* src, uint32_t bytes,
                                        uint32_t mbar) {
    asm volatile("cp.async.bulk.shared::cta.global.mbarrier::complete_tx::bytes "
                 "[%0], [%1], %2, [%3];"
                 :: "r"(dst), "l"(src), "r"(bytes), "r"(mbar) : "memory");
}
#define MBARRIER_INIT(mbar, cnt) \
    asm volatile("mbarrier.init.shared.b64 [%0], %1;" :: "r"((uint32_t)(mbar)), "r"((uint32_t)(cnt)) : "memory")
#define MBARRIER_EXPECT_TX(mbar, bytes) \
    asm volatile("mbarrier.arrive.expect_tx.shared.b64 _, [%0], %1;" \
        :: "r"((uint32_t)(mbar)), "r"((uint32_t)(bytes)) : "memory")
#define MBARRIER_WAIT_PARITY(mbar, parity) do { \
    uint32_t _m = (uint32_t)(mbar); uint32_t _p = (uint32_t)(parity); uint32_t _d; \
    asm volatile("{\n\t.reg .pred p;\n\t" \
        "mbarrier.try_wait.parity.acquire.cta.shared::cta.b64 p, [%1], %2;\n\t" \
        "selp.b32 %0, 1, 0, p;\n\t}" : "=r"(_d) : "r"(_m), "r"(_p) : "memory"); \
    if (!_d) { \
        asm volatile("{\n\t.reg .pred P1;\n\tWL_%=:\n\t" \
            "mbarrier.try_wait.parity.acquire.cta.shared::cta.b64 P1, [%0], %1, 0x989680;\n\t" \
            "@P1 bra.uni WD_%=;\n\tbra.uni WL_%=;\n\tWD_%=:\n\t}" \
            :: "r"(_m), "r"(_p) : "memory"); \
    } } while (0)

__device__ __forceinline__ void ldsm_x4(uint32_t& r0, uint32_t& r1, uint32_t& r2, uint32_t& r3,
                                        uint32_t addr) {
    asm volatile("ldmatrix.sync.aligned.m8n8.x4.shared.b16 {%0,%1,%2,%3}, [%4];"
                 : "=r"(r0), "=r"(r1), "=r"(r2), "=r"(r3) : "r"(addr));
}
__device__ __forceinline__ void mma_bf16(float* c,
                                         uint32_t a0, uint32_t a1, uint32_t a2, uint32_t a3,
                                         uint32_t b0, uint32_t b1) {
    asm volatile("mma.sync.aligned.m16n8k16.row.col.f32.bf16.bf16.f32 "
                 "{%0,%1,%2,%3}, {%4,%5,%6,%7}, {%8,%9}, {%0,%1,%2,%3};"
                 : "+f"(c[0]), "+f"(c[1]), "+f"(c[2]), "+f"(c[3])
                 : "r"(a0), "r"(a1), "r"(a2), "r"(a3), "r"(b0), "r"(b1));
}
#define SWZ(off) ((off) ^ (((off) >> 3) & 0x70))

__device__ __forceinline__ float sigf(float x) { return 1.0f / (1.0f + __expf(-x)); }
__device__ __forceinline__ float tanh_fast(float x) {
    float a = fabsf(x);
    float e = __expf(-2.0f * a);
    float t = (1.0f - e) / (1.0f + e);
    return copysignf(t, x);
}

// ---------------------------------------------------------------------------
// Phase 0a: split Wh (h-part) into packed bf16 hi/lo. Row n=(j<<2)|gate.
// ---------------------------------------------------------------------------
__global__ __launch_bounds__(256) void conv_w(
    const float* __restrict__ Wf, const float* __restrict__ Wi,
    const float* __restrict__ Wu, const float* __restrict__ Wo,
    __nv_bfloat16* __restrict__ hi, __nv_bfloat16* __restrict__ lo)
{
    size_t idx = (size_t)blockIdx.x * 256 + threadIdx.x;   // over NG_*H_
    int n = (int)(idx >> 10);
    int k = (int)(idx & 1023);
    int j = n >> 2, gate = n & 3;
    const float* W = (gate == 0) ? Wf : (gate == 1) ? Wi : (gate == 2) ? Wu : Wo;
    float w = W[(size_t)j * DH_ + D_ + k];
    __nv_bfloat16 h16 = __float2bfloat16(w);
    hi[idx] = h16;
    lo[idx] = __float2bfloat16(w - __bfloat162float(h16));
}

// Phase 0b: split Wx (x-part) into packed bf16 hi/lo. Row n=(j<<2)|gate.
__global__ __launch_bounds__(256) void conv_wx(
    const float* __restrict__ Wf, const float* __restrict__ Wi,
    const float* __restrict__ Wu, const float* __restrict__ Wo,
    __nv_bfloat16* __restrict__ hi, __nv_bfloat16* __restrict__ lo)
{
    size_t idx = (size_t)blockIdx.x * 256 + threadIdx.x;   // over NG_*D_
    int n = (int)(idx >> 10);
    int k = (int)(idx & 1023);
    int j = n >> 2, gate = n & 3;
    const float* W = (gate == 0) ? Wf : (gate == 1) ? Wi : (gate == 2) ? Wu : Wo;
    float w = W[(size_t)j * DH_ + k];
    __nv_bfloat16 h16 = __float2bfloat16(w);
    hi[idx] = h16;
    lo[idx] = __float2bfloat16(w - __bfloat162float(h16));
}

// Phase 0c: split X into bf16 hi/lo.
__global__ __launch_bounds__(256) void conv_x(
    const float* __restrict__ X,
    __nv_bfloat16* __restrict__ hi, __nv_bfloat16* __restrict__ lo)
{
    size_t idx = (size_t)blockIdx.x * 256 + threadIdx.x;   // over M_*D_
    float x = X[idx];
    __nv_bfloat16 h16 = __float2bfloat16(x);
    hi[idx] = h16;
    lo[idx] = __float2bfloat16(x - __bfloat162float(h16));
}

// ---------------------------------------------------------------------------
// Phase 1: input projection on tensor cores (split bf16).
// Z written in per-CTA slab layout: zidx(m,n) =
//   ((m>>6)*128 + (n>>5))*2048 + (m&63)*32 + (n&31)
// ---------------------------------------------------------------------------
#define GS_(s)   ((s) * 65536)
#define GA_HI(s) (GS_(s) + 0)
#define GA_LO(s) (GS_(s) + 16384)
#define GB_HI(s) (GS_(s) + 32768)
#define GB_LO(s) (GS_(s) + 49152)
#define GSMEM_   131072

__global__ __launch_bounds__(256) void gemm_tc(
    const __nv_bfloat16* __restrict__ Xh, const __nv_bfloat16* __restrict__ Xl,
    const __nv_bfloat16* __restrict__ Wxh, const __nv_bfloat16* __restrict__ Wxl,
    const float* __restrict__ bf, const float* __restrict__ bi,
    const float* __restrict__ bu, const float* __restrict__ bo,
    float* __restrict__ Z)
{
    extern __shared__ __align__(1024) char sm[];
    __shared__ float s_bias[128];

    const uint32_t sbase = smem_u32(sm);
    const int tid  = threadIdx.x;
    const int wid  = tid >> 5;
    const int lane = tid & 31;
    const int n0   = blockIdx.x * 128;   // packed col base
    const int m0   = blockIdx.y * 128;

    const int wm = wid & 1;              // M half (64 rows)
    const int wn = wid >> 1;             // N quarter (32 cols)

    if (tid < 128) {
        int n = n0 + tid, gate = n & 3, j = n >> 2;
        const float* Ba = (gate == 0) ? bf : (gate == 1) ? bi : (gate == 2) ? bu : bo;
        s_bias[tid] = Ba[j];
    }

    const char* xh8 = (const char*)(Xh + (size_t)m0 * D_);
    const char* xl8 = (const char*)(Xl + (size_t)m0 * D_);
    const char* wh8 = (const char*)(Wxh + (size_t)n0 * D_);
    const char* wl8 = (const char*)(Wxl + (size_t)n0 * D_);

    auto load_chunk = [&](int ch, int s) {
#pragma unroll
        for (int r4 = 0; r4 < 4; r4++) {
            int idx = tid + r4 * 256;
            int row = idx >> 3, cg = idx & 7;
            size_t goff = (size_t)row * 2048 + (size_t)ch * 128 + cg * 16;
            uint32_t soff = SWZ((uint32_t)(row * 128 + cg * 16));
            cp_async16(sbase + GA_HI(s) + soff, xh8 + goff);
            cp_async16(sbase + GA_LO(s) + soff, xl8 + goff);
            cp_async16(sbase + GB_HI(s) + soff, wh8 + goff);
            cp_async16(sbase + GB_LO(s) + soff, wl8 + goff);
        }
    };

    float acc[4][4][4];
#pragma unroll
    for (int mt = 0; mt < 4; mt++)
#pragma unroll
        for (int nt = 0; nt < 4; nt++)
#pragma unroll
            for (int i = 0; i < 4; i++) acc[mt][nt][i] = 0.0f;

    const uint32_t a_kb = (uint32_t)((lane >> 4) << 3);
    const uint32_t b_nt = (uint32_t)((lane >> 3) >> 1);
    const uint32_t b_kb = (uint32_t)(((lane >> 3) & 1) * 8);
    const uint32_t b_r  = (uint32_t)(lane & 7);

    load_chunk(0, 0);
    CP_COMMIT();

    for (int ch = 0; ch < 16; ch++) {
        const int s = ch & 1;
        if (ch + 1 < 16) {
            load_chunk(ch + 1, s ^ 1);
            CP_COMMIT();
            CP_WAIT(1);
        } else {
            CP_WAIT(0);
        }
        __syncthreads();

        const uint32_t Ah = sbase + GA_HI(s), Al = sbase + GA_LO(s);
        const uint32_t Bh = sbase + GB_HI(s), Bl = sbase + GB_LO(s);

#pragma unroll
        for (int ks = 0; ks < 4; ks++) {
            uint32_t ah[4][4], al[4][4];
#pragma unroll
            for (int mt = 0; mt < 4; mt++) {
                uint32_t row = (uint32_t)(wm * 64 + mt * 16 + (lane & 15));
                uint32_t aoff = SWZ((row << 7) + (ks * 16 + a_kb) * 2);
                ldsm_x4(ah[mt][0], ah[mt][1], ah[mt][2], ah[mt][3], Ah + aoff);
                ldsm_x4(al[mt][0], al[mt][1], al[mt][2], al[mt][3], Al + aoff);
            }
            uint32_t bh[8], bl[8];
#pragma unroll
            for (int np = 0; np < 2; np++) {
                uint32_t row = (uint32_t)(wn * 32) + (np * 2 + b_nt) * 8 + b_r;
                uint32_t boff = SWZ((row << 7) + (ks * 16 + b_kb) * 2);
                ldsm_x4(bh[np*4+0], bh[np*4+1], bh[np*4+2], bh[np*4+3], Bh + boff);
                ldsm_x4(bl[np*4+0], bl[np*4+1], bl[np*4+2], bl[np*4+3], Bl + boff);
            }
#pragma unroll
            for (int mt = 0; mt < 4; mt++)
#pragma unroll
                for (int nt = 0; nt < 4; nt++) {
                    mma_bf16(acc[mt][nt], ah[mt][0], ah[mt][1], ah[mt][2], ah[mt][3],
                             bh[nt*2], bh[nt*2+1]);
                    mma_bf16(acc[mt][nt], ah[mt][0], ah[mt][1], ah[mt][2], ah[mt][3],
                             bl[nt*2], bl[nt*2+1]);
                    mma_bf16(acc[mt][nt], al[mt][0], al[mt][1], al[mt][2], al[mt][3],
                             bh[nt*2], bh[nt*2+1]);
                }
        }
        __syncthreads();
    }

    const int g  = lane >> 2;
    const int tg = lane & 3;
#pragma unroll
    for (int mt = 0; mt < 4; mt++) {
        int r0 = m0 + wm * 64 + mt * 16 + g;
#pragma unroll
        for (int nt = 0; nt < 4; nt++) {
            int nl = wn * 32 + nt * 8 + tg * 2;
            int n  = n0 + nl;
            float bia0 = s_bias[nl], bia1 = s_bias[nl + 1];
            float2 v0 = make_float2(acc[mt][nt][0] + bia0, acc[mt][nt][1] + bia1);
            float2 v1 = make_float2(acc[mt][nt][2] + bia0, acc[mt][nt][3] + bia1);
            size_t z0 = ((size_t)(r0 >> 6) * 128 + (n >> 5)) * 2048 + (r0 & 63) * 32 + (n & 31);
            int r1 = r0 + 8;
            size_t z1 = ((size_t)(r1 >> 6) * 128 + (n >> 5)) * 2048 + (r1 & 63) * 32 + (n & 31);
            *(float2*)&Z[z0] = v0;
            *(float2*)&Z[z1] = v1;
        }
    }
}

// ---------------------------------------------------------------------------
// Phase 2: persistent recurrence v3 — bulk-copy A loads.
// 128 CTAs, 256 threads (8 warps; wm 0..3 x wn 0..1).
// h stored pre-swizzled chunk-major in global; per 128-col chunk one thread
// issues 4x8KB cp.async.bulk (hi/lo x 2 sub-chunks) + mbarrier expect_tx.
// SMEM: W 128K | A 2 stages x 32K | ZX 8K. Zs overlays A stage 0.
// ---------------------------------------------------------------------------
#define W_HI_     0
#define W_LO_     65536
#define AST_(s)   (131072 + (s) * 32768)
#define ZX_OFF_   196608
#define ZS_OFF_   131072
#define SMEM_DYN_ 204800

__global__ __launch_bounds__(256) void lstm_persist(
    const float* __restrict__ Zx_all,
    const __nv_bfloat16* __restrict__ Whh,
    const __nv_bfloat16* __restrict__ Whl,
    char* __restrict__ Hsw,            // g_hsw base
    const float* __restrict__ gbf, const float* __restrict__ gbi,
    const float* __restrict__ gbu, const float* __restrict__ gbo,
    float* __restrict__ out,           // [T][B][H]
    float* __restrict__ hc_tail)       // null or [hx|cx]
{
    extern __shared__ __align__(1024) char sm[];
    __shared__ float s_gb[32];
    __shared__ __align__(8) uint64_t s_mbar[3];   // stage0, stage1, zx

    const uint32_t sbase = smem_u32(sm);
    const int tid  = threadIdx.x;
    const int wid  = tid >> 5;
    const int lane = tid & 31;
    const int bx   = blockIdx.x;
    const int j0   = bx * 8;

    if (tid < 32) {
        int gate = tid >> 3, jl = tid & 7;
        const float* gp = (gate == 0) ? gbf : (gate == 1) ? gbi : (gate == 2) ? gbu : gbo;
        s_gb[tid] = gp[j0 + jl];
    }
    if (tid == 0) {
        MBARRIER_INIT(smem_u32(&s_mbar[0]), 1);
        MBARRIER_INIT(smem_u32(&s_mbar[1]), 1);
        MBARRIER_INIT(smem_u32(&s_mbar[2]), 1);
    }

    // ---- resident weights once (cp.async fine: one-time) ----
    {
        const char* wh8 = (const char*)(Whh + (size_t)bx * 32 * H_);
        const char* wl8 = (const char*)(Whl + (size_t)bx * 32 * H_);
        for (int i = tid; i < 4096; i += 256) {
            int c  = i >> 8;
            int r  = (i >> 3) & 31;
            int cg = i & 7;
            size_t goff = (size_t)r * 2048 + (size_t)c * 128 + cg * 16;
            uint32_t soff = (uint32_t)c * 4096 + SWZ((uint32_t)(r * 128 + cg * 16));
            cp_async16(sbase + W_HI_ + soff, wh8 + goff);
            cp_async16(sbase + W_LO_ + soff, wl8 + goff);
        }
        CP_COMMIT(); CP_WAIT(0);
        __syncthreads();
    }

    const int wm = wid & 3;
    const int wn = wid >> 2;
    const int m0 = wm * 16;

    const uint32_t a_r  = (uint32_t)(m0 + (lane & 15));
    const uint32_t a_kb = (uint32_t)((lane >> 4) << 3);
    const uint32_t b_nt = (uint32_t)((lane >> 3) >> 1);
    const uint32_t b_kb = (uint32_t)(((lane >> 3) & 1) * 8);
    const uint32_t b_r  = (uint32_t)(lane & 7);
    const uint32_t b_row = (uint32_t)(wn * 16) + b_nt * 8 + b_r;

    const uint32_t mb0 = smem_u32(&s_mbar[0]);
    const uint32_t mb1 = smem_u32(&s_mbar[1]);
    const uint32_t mbz = smem_u32(&s_mbar[2]);

    int ph[2] = {0, 0};
    int phz = 0;

    float c_reg[2] = {0.f, 0.f};

    const int hc64 = j0 >> 6;          // this CTA's h chunk for its j slice
    const int kcb  = j0 & 63;

    for (int t = 0; t < T_; t++) {
        const char* hin = Hsw + (size_t)(t & 1) * HBUF_STRIDE_;
        char* hout = Hsw + (size_t)((t + 1) & 1) * HBUF_STRIDE_;

        // issue step's first copies (tid 0)
        if (tid == 0) {
            asm volatile("fence.proxy.async;" ::: "memory");
            MBARRIER_EXPECT_TX(mbz, 8192);
            cp_bulk(sbase + ZX_OFF_,
                    Zx_all + ((size_t)t * 128 + bx) * 2048, 8192, mbz);
#pragma unroll
            for (int pc = 0; pc < 2; pc++) {   // chunks 0,1 -> stages 0,1
                uint32_t mb = pc ? mb1 : mb0;
                MBARRIER_EXPECT_TX(mb, 32768);
#pragma unroll
                for (int sub = 0; sub < 2; sub++) {
                    int c64 = pc * 2 + sub;
                    cp_bulk(sbase + AST_(pc) + sub * 8192,
                            hin + (size_t)c64 * 8192, 8192, mb);
                    cp_bulk(sbase + AST_(pc) + 16384 + sub * 8192,
                            hin + HHALF_STRIDE_ + (size_t)c64 * 8192, 8192, mb);
                }
            }
        }

        float acc[2][4];
#pragma unroll
        for (int nt = 0; nt < 2; nt++)
#pragma unroll
            for (int i = 0; i < 4; i++) acc[nt][i] = 0.0f;

        for (int ch = 0; ch < 8; ch++) {
            const int s = ch & 1;
            MBARRIER_WAIT_PARITY(s ? mb1 : mb0, ph[s]);
            ph[s] ^= 1;

#pragma unroll
            for (int sub = 0; sub < 2; sub++) {
                const int c64 = ch * 2 + sub;
                const uint32_t Ah = sbase + AST_(s) + sub * 8192;
                const uint32_t Al = Ah + 16384;
                const uint32_t Bh = sbase + W_HI_ + (uint32_t)c64 * 4096;
                const uint32_t Bl = sbase + W_LO_ + (uint32_t)c64 * 4096;

#pragma unroll
                for (int ks = 0; ks < 4; ks++) {
                    uint32_t aoff = SWZ((a_r << 7) + (ks * 16 + a_kb) * 2);
                    uint32_t ah0, ah1, ah2, ah3, al0, al1, al2, al3;
                    ldsm_x4(ah0, ah1, ah2, ah3, Ah + aoff);
                    ldsm_x4(al0, al1, al2, al3, Al + aoff);

                    uint32_t boff = SWZ((b_row << 7) + (ks * 16 + b_kb) * 2);
                    uint32_t bh0, bh1, bh2, bh3, bl0, bl1, bl2, bl3;
                    ldsm_x4(bh0, bh1, bh2, bh3, Bh + boff);
                    ldsm_x4(bl0, bl1, bl2, bl3, Bl + boff);

                    mma_bf16(acc[0], ah0, ah1, ah2, ah3, bh0, bh1);
                    mma_bf16(acc[0], ah0, ah1, ah2, ah3, bl0, bl1);
                    mma_bf16(acc[0], al0, al1, al2, al3, bh0, bh1);
                    mma_bf16(acc[1], ah0, ah1, ah2, ah3, bh2, bh3);
                    mma_bf16(acc[1], ah0, ah1, ah2, ah3, bl2, bl3);
                    mma_bf16(acc[1], al0, al1, al2, al3, bh2, bh3);
                }
            }
            __syncthreads();

            if (ch + 2 < 8 && tid == 0) {
                uint32_t mb = s ? mb1 : mb0;
                MBARRIER_EXPECT_TX(mb, 32768);
#pragma unroll
                for (int sub = 0; sub < 2; sub++) {
                    int c64 = (ch + 2) * 2 + sub;
                    cp_bulk(sbase + AST_(s) + sub * 8192,
                            hin + (size_t)c64 * 8192, 8192, mb);
                    cp_bulk(sbase + AST_(s) + 16384 + sub * 8192,
                            hin + HHALF_STRIDE_ + (size_t)c64 * 8192, 8192, mb);
                }
            }
        }

        // stage accumulators to SMEM (overlay A stage 0)
        float* Zs = (float*)(sm + ZS_OFF_);
        {
            const int g  = lane >> 2;
            const int tg = lane & 3;
#pragma unroll
            for (int nt = 0; nt < 2; nt++) {
                int n = wn * 16 + nt * 8 + tg * 2;
                Zs[(m0 + g)     * 32 + n]     = acc[nt][0];
                Zs[(m0 + g)     * 32 + n + 1] = acc[nt][1];
                Zs[(m0 + g + 8) * 32 + n]     = acc[nt][2];
                Zs[(m0 + g + 8) * 32 + n + 1] = acc[nt][3];
            }
        }
        __syncthreads();
        MBARRIER_WAIT_PARITY(mbz, phz);
        phz ^= 1;

        // fused LSTM epilogue: 512 (b, jl) pairs, 2 per thread, c in registers
        const float* zxs = (const float*)(sm + ZX_OFF_);
        float* out_t = out + (size_t)t * BH_;
        char* hout_hi = hout + (size_t)hc64 * 8192;
        char* hout_lo = hout + HHALF_STRIDE_ + (size_t)hc64 * 8192;
#pragma unroll
        for (int p0 = 0; p0 < 2; p0++) {
            int p  = tid + p0 * 256;
            int b  = p >> 3;
            int jl = p & 7;
            float4 zh  = *(const float4*)&Zs[b * 32 + jl * 4];
            float4 zx4 = *(const float4*)&zxs[b * 32 + jl * 4];

            float f  = sigf(__cosf(zh.x + zx4.x) + s_gb[0 * 8 + jl]);
            float ii = sigf(__cosf(zh.y + zx4.y) + s_gb[1 * 8 + jl]);
            float g  = tanh_fast(__cosf(zh.z + zx4.z) + s_gb[2 * 8 + jl]);
            float o  = sigf(__cosf(zh.w + zx4.w) + s_gb[3 * 8 + jl]);

            float c = f * c_reg[p0] + ii * g;
            c_reg[p0] = c;
            float h = o * tanh_fast(c);

            size_t idx = (size_t)b * H_ + j0 + jl;
            out_t[idx] = h;

            __nv_bfloat16 hhi = __float2bfloat16(h);
            __nv_bfloat16 hlo = __float2bfloat16(h - __bfloat162float(hhi));
            uint32_t hoff = SWZ((uint32_t)(b * 128 + (kcb + jl) * 2));
            *(__nv_bfloat16*)(hout_hi + hoff) = hhi;
            *(__nv_bfloat16*)(hout_lo + hoff) = hlo;

            if (hc_tail && t == T_ - 1) {
                hc_tail[idx] = h;
                hc_tail[(size_t)BH_ + idx] = c;
            }
        }

        // grid barrier (skip after last step)
        if (t + 1 < T_) {
            __syncthreads();
            if (tid == 0) {
                asm volatile("red.release.gpu.add.u32 [%0], 1;" :: "l"(&g_bar) : "memory");
                unsigned target = (unsigned)(t + 1) * 128u;
                unsigned v;
                do {
                    asm volatile("ld.acquire.gpu.u32 %0, [%1];" : "=r"(v) : "l"(&g_bar) : "memory");
                } while (v < target);
            }
            __syncthreads();
        }
    }
}

// ---------------------------------------------------------------------------
extern "C" void kernel_launch(void* const* d_in, const int* in_sizes, int n_in,
                              void* d_out, int out_size)
{
    const float* X   = (const float*)d_in[0];
    const float* Wf  = (const float*)d_in[1];
    const float* bf  = (const float*)d_in[2];
    const float* gbf = (const float*)d_in[3];
    const float* Wi  = (const float*)d_in[4];
    const float* bi  = (const float*)d_in[5];
    const float* gbi = (const float*)d_in[6];
    const float* Wu  = (const float*)d_in[7];
    const float* bu  = (const float*)d_in[8];
    const float* gbu = (const float*)d_in[9];
    const float* Wo  = (const float*)d_in[10];
    const float* bo  = (const float*)d_in[11];
    const float* gbo = (const float*)d_in[12];

    float* out = (float*)d_out;

    float *p_zx;
    __nv_bfloat16 *p_whh, *p_whl, *p_wxh, *p_wxl, *p_xh, *p_xl;
    char* p_hsw;
    unsigned* p_bar;
    cudaGetSymbolAddress((void**)&p_zx,  g_zx);
    cudaGetSymbolAddress((void**)&p_whh, g_whh);
    cudaGetSymbolAddress((void**)&p_whl, g_whl);
    cudaGetSymbolAddress((void**)&p_wxh, g_wxh);
    cudaGetSymbolAddress((void**)&p_wxl, g_wxl);
    cudaGetSymbolAddress((void**)&p_xh,  g_xh);
    cudaGetSymbolAddress((void**)&p_xl,  g_xl);
    cudaGetSymbolAddress((void**)&p_hsw, g_hsw);
    cudaGetSymbolAddress((void**)&p_bar, g_bar);

    cudaFuncSetAttribute(lstm_persist, cudaFuncAttributeMaxDynamicSharedMemorySize, SMEM_DYN_);
    cudaFuncSetAttribute(gemm_tc, cudaFuncAttributeMaxDynamicSharedMemorySize, GSMEM_);

    // reset initial h buffer (parity 0) and the barrier counter
    cudaMemsetAsync(p_hsw, 0, HBUF_STRIDE_);
    cudaMemsetAsync(p_bar, 0, sizeof(unsigned));

    // Phase 0: split weights and inputs to bf16 hi/lo
    conv_w<<<(NG_ * H_) / 256, 256>>>(Wf, Wi, Wu, Wo, p_whh, p_whl);
    conv_wx<<<(NG_ * D_) / 256, 256>>>(Wf, Wi, Wu, Wo, p_wxh, p_wxl);
    conv_x<<<(M_ * D_) / 256, 256>>>(X, p_xh, p_xl);

    // Phase 1: all-timestep input projection (+bias) on tensor cores
    dim3 g1(NG_ / 128, M_ / 128);
    gemm_tc<<<g1, 256, GSMEM_>>>(p_xh, p_xl, p_wxh, p_wxl, bf, bi, bu, bo, p_zx);

    // Phase 2: persistent fused recurrence (all 256 steps in one kernel)
    const size_t TBH = (size_t)T_ * B_ * H_;
    const bool tails = out_size >= (int)(TBH + 2 * (size_t)BH_);
    lstm_persist<<<128, 256, SMEM_DYN_>>>(
        p_zx, p_whh, p_whl, p_hsw,
        gbf, gbi, gbu, gbo,
        out, tails ? out + TBH : nullptr);
}